// round 1
// baseline (speedup 1.0000x reference)
#include <cuda_runtime.h>
#include <math.h>

#define XLEN 2048
#define YLEN 1024
#define BSZ  8
#define XD   1024
#define YD   1024
#define HD   512
#define YOUT 1024
#define FMAXV 3.402823466e38f
#define INV_SQRT_HD 0.04419417382415922f   // 1/sqrt(512)

// -------- scratch (device globals: allocation-free) --------
__device__ float g_xk[XLEN * BSZ * HD];       // 32 MB
__device__ float g_xv[XLEN * BSZ * HD];       // 32 MB
__device__ float g_yq[YLEN * BSZ * HD];       // 16 MB
__device__ float g_logits[BSZ * YLEN * XLEN]; // 64 MB (logits -> attn in place)
__device__ float g_af[YLEN * BSZ * HD];       // 16 MB

// ============================================================
// Generic TN GEMM: C[M,N] = A(M,K;lda) @ B(N,K;ldb)^T (+bias)(+accum)
// 64x64 tile, BK=16, 256 threads, 4x4 per thread.
// ============================================================
__global__ __launch_bounds__(256) void gemm_tn_bias(
    const float* __restrict__ A, int lda,
    const float* __restrict__ Bm, int ldb,
    float* __restrict__ C, int ldc,
    const float* __restrict__ bias,
    int K, int accum)
{
    __shared__ float As[16][68];
    __shared__ float Bs[16][68];

    const int tid = threadIdx.x;
    const int tx = tid & 15, ty = tid >> 4;
    const int row0 = blockIdx.y * 64, col0 = blockIdx.x * 64;
    const int lm = tid >> 2;          // 0..63
    const int lk = (tid & 3) << 2;    // 0,4,8,12

    const float* Aptr = A + (size_t)(row0 + lm) * lda + lk;
    const float* Bptr = Bm + (size_t)(col0 + lm) * ldb + lk;

    float acc[4][4] = {};

    for (int k0 = 0; k0 < K; k0 += 16) {
        float4 av = *(const float4*)(Aptr + k0);
        float4 bv = *(const float4*)(Bptr + k0);
        As[lk + 0][lm] = av.x; As[lk + 1][lm] = av.y;
        As[lk + 2][lm] = av.z; As[lk + 3][lm] = av.w;
        Bs[lk + 0][lm] = bv.x; Bs[lk + 1][lm] = bv.y;
        Bs[lk + 2][lm] = bv.z; Bs[lk + 3][lm] = bv.w;
        __syncthreads();
#pragma unroll
        for (int kk = 0; kk < 16; kk++) {
            float4 a = *(const float4*)&As[kk][ty * 4];
            float4 b = *(const float4*)&Bs[kk][tx * 4];
            float ar[4] = {a.x, a.y, a.z, a.w};
            float br[4] = {b.x, b.y, b.z, b.w};
#pragma unroll
            for (int i = 0; i < 4; i++)
#pragma unroll
                for (int j = 0; j < 4; j++)
                    acc[i][j] += ar[i] * br[j];
        }
        __syncthreads();
    }

#pragma unroll
    for (int i = 0; i < 4; i++) {
        int r = row0 + ty * 4 + i;
#pragma unroll
        for (int j = 0; j < 4; j++) {
            int c = col0 + tx * 4 + j;
            float v = acc[i][j];
            if (bias) v += bias[c];
            size_t off = (size_t)r * ldc + c;
            if (accum) v += C[off];
            C[off] = v;
        }
    }
}

// ============================================================
// Batched logits: logit[b,y,x] = dot(yq[y,b,:], xk[x,b,:]) * scale
//                 + sigmoid(align_w)*alignment ; clamp ; pad-mask
// grid.z = batch
// ============================================================
__global__ __launch_bounds__(256) void logits_kernel(
    const float* __restrict__ alignment,
    const int*   __restrict__ mask,
    const float* __restrict__ align_w)
{
    __shared__ float As[16][68];
    __shared__ float Bs[16][68];

    const int b = blockIdx.z;
    const float* A  = g_yq + b * HD;   // rows y, stride BSZ*HD
    const float* Bm = g_xk + b * HD;   // rows x, stride BSZ*HD
    const int lda = BSZ * HD;

    const int tid = threadIdx.x;
    const int tx = tid & 15, ty = tid >> 4;
    const int row0 = blockIdx.y * 64, col0 = blockIdx.x * 64;
    const int lm = tid >> 2;
    const int lk = (tid & 3) << 2;

    const float* Aptr = A + (size_t)(row0 + lm) * lda + lk;
    const float* Bptr = Bm + (size_t)(col0 + lm) * lda + lk;

    float acc[4][4] = {};

    for (int k0 = 0; k0 < HD; k0 += 16) {
        float4 av = *(const float4*)(Aptr + k0);
        float4 bv = *(const float4*)(Bptr + k0);
        As[lk + 0][lm] = av.x; As[lk + 1][lm] = av.y;
        As[lk + 2][lm] = av.z; As[lk + 3][lm] = av.w;
        Bs[lk + 0][lm] = bv.x; Bs[lk + 1][lm] = bv.y;
        Bs[lk + 2][lm] = bv.z; Bs[lk + 3][lm] = bv.w;
        __syncthreads();
#pragma unroll
        for (int kk = 0; kk < 16; kk++) {
            float4 a = *(const float4*)&As[kk][ty * 4];
            float4 b2 = *(const float4*)&Bs[kk][tx * 4];
            float ar[4] = {a.x, a.y, a.z, a.w};
            float br[4] = {b2.x, b2.y, b2.z, b2.w};
#pragma unroll
            for (int i = 0; i < 4; i++)
#pragma unroll
                for (int j = 0; j < 4; j++)
                    acc[i][j] += ar[i] * br[j];
        }
        __syncthreads();
    }

    const float sig = 1.0f / (1.0f + expf(-align_w[0]));
    const size_t base = (size_t)b * YLEN * XLEN;
#pragma unroll
    for (int i = 0; i < 4; i++) {
        int r = row0 + ty * 4 + i;
#pragma unroll
        for (int j = 0; j < 4; j++) {
            int c = col0 + tx * 4 + j;
            size_t off = base + (size_t)r * XLEN + c;
            float v = acc[i][j] * INV_SQRT_HD + sig * alignment[off];
            v = fmaxf(v, -FMAXV);
            if (mask[off] != 0) v = fmaxf(v - FMAXV, -FMAXV);
            g_logits[off] = v;
        }
    }
}

// ============================================================
// Row softmax over x (2048), in place in g_logits.
// One block per (b,y) row; 256 threads * 8 elements.
// ============================================================
__global__ __launch_bounds__(256) void softmax_kernel()
{
    const int row = blockIdx.x;
    float* p = g_logits + (size_t)row * XLEN;
    const int tid = threadIdx.x;

    float v[8];
    float mx = -FMAXV;
#pragma unroll
    for (int i = 0; i < 8; i++) {
        v[i] = p[tid + (i << 8)];
        mx = fmaxf(mx, v[i]);
    }

    __shared__ float sred[8];
#pragma unroll
    for (int o = 16; o > 0; o >>= 1)
        mx = fmaxf(mx, __shfl_xor_sync(0xffffffff, mx, o));
    if ((tid & 31) == 0) sred[tid >> 5] = mx;
    __syncthreads();
    mx = sred[0];
#pragma unroll
    for (int w = 1; w < 8; w++) mx = fmaxf(mx, sred[w]);
    __syncthreads();

    float s = 0.0f;
#pragma unroll
    for (int i = 0; i < 8; i++) {
        v[i] = expf(v[i] - mx);
        s += v[i];
    }
#pragma unroll
    for (int o = 16; o > 0; o >>= 1)
        s += __shfl_xor_sync(0xffffffff, s, o);
    if ((tid & 31) == 0) sred[tid >> 5] = s;
    __syncthreads();
    s = 0.0f;
#pragma unroll
    for (int w = 0; w < 8; w++) s += sred[w];

    const float inv = 1.0f / s;
#pragma unroll
    for (int i = 0; i < 8; i++)
        p[tid + (i << 8)] = v[i] * inv;
}

// ============================================================
// Batched NN GEMM: af[y,b,h] = sum_x attn[b,y,x] * xv[x,b,h]
// grid.z = batch. M=YLEN, N=HD, K=XLEN.
// ============================================================
__global__ __launch_bounds__(256) void attnfeat_kernel()
{
    __shared__ float As[16][68];
    __shared__ float Bs[16][68];

    const int b = blockIdx.z;
    const float* A = g_logits + (size_t)b * YLEN * XLEN;  // attn rows y
    float* C = g_af + b * HD;                             // row stride BSZ*HD

    const int tid = threadIdx.x;
    const int tx = tid & 15, ty = tid >> 4;
    const int row0 = blockIdx.y * 64, col0 = blockIdx.x * 64;

    // A load (transpose into shared): same scheme as TN
    const int lm = tid >> 2;
    const int lk = (tid & 3) << 2;
    const float* Aptr = A + (size_t)(row0 + lm) * XLEN + lk;

    // B load: Bs[kk][n] = xv[(k0+kk)*BSZ*HD + b*HD + col0 + n]
    const int bkk = tid >> 4;          // 0..15
    const int bn  = (tid & 15) << 2;   // 0,4,...,60
    const float* Bptr = g_xv + (size_t)bkk * (BSZ * HD) + b * HD + col0 + bn;

    float acc[4][4] = {};

    for (int k0 = 0; k0 < XLEN; k0 += 16) {
        float4 av = *(const float4*)(Aptr + k0);
        As[lk + 0][lm] = av.x; As[lk + 1][lm] = av.y;
        As[lk + 2][lm] = av.z; As[lk + 3][lm] = av.w;
        float4 bv = *(const float4*)(Bptr + (size_t)k0 * (BSZ * HD));
        *(float4*)&Bs[bkk][bn] = bv;
        __syncthreads();
#pragma unroll
        for (int kk = 0; kk < 16; kk++) {
            float4 a = *(const float4*)&As[kk][ty * 4];
            float4 b2 = *(const float4*)&Bs[kk][tx * 4];
            float ar[4] = {a.x, a.y, a.z, a.w};
            float br[4] = {b2.x, b2.y, b2.z, b2.w};
#pragma unroll
            for (int i = 0; i < 4; i++)
#pragma unroll
                for (int j = 0; j < 4; j++)
                    acc[i][j] += ar[i] * br[j];
        }
        __syncthreads();
    }

#pragma unroll
    for (int i = 0; i < 4; i++) {
        int r = row0 + ty * 4 + i;
#pragma unroll
        for (int j = 0; j < 4; j++) {
            int c = col0 + tx * 4 + j;
            C[(size_t)r * (BSZ * HD) + c] = acc[i][j];
        }
    }
}

// ============================================================
// Launch
// ============================================================
extern "C" void kernel_launch(void* const* d_in, const int* in_sizes, int n_in,
                              void* d_out, int out_size)
{
    const float* X         = (const float*)d_in[0];
    const float* Y         = (const float*)d_in[1];
    const float* alignment = (const float*)d_in[2];
    const int*   mask      = (const int*)d_in[3];
    const float* Xk_w      = (const float*)d_in[4];
    const float* Xk_b      = (const float*)d_in[5];
    const float* Xv_w      = (const float*)d_in[6];
    const float* Xv_b      = (const float*)d_in[7];
    const float* Yq_w      = (const float*)d_in[8];
    const float* Yq_b      = (const float*)d_in[9];
    const float* Yw_w      = (const float*)d_in[10];
    const float* Yw_b      = (const float*)d_in[11];
    const float* align_w   = (const float*)d_in[12];
    float* out = (float*)d_out;

    float *xk_p, *xv_p, *yq_p, *af_p;
    cudaGetSymbolAddress((void**)&xk_p, g_xk);
    cudaGetSymbolAddress((void**)&xv_p, g_xv);
    cudaGetSymbolAddress((void**)&yq_p, g_yq);
    cudaGetSymbolAddress((void**)&af_p, g_af);

    // xk = X @ Xk_w^T + b   : M=16384, N=512, K=1024
    gemm_tn_bias<<<dim3(HD / 64, (XLEN * BSZ) / 64), 256>>>(
        X, XD, Xk_w, XD, xk_p, HD, Xk_b, XD, 0);
    // xv = X @ Xv_w^T + b
    gemm_tn_bias<<<dim3(HD / 64, (XLEN * BSZ) / 64), 256>>>(
        X, XD, Xv_w, XD, xv_p, HD, Xv_b, XD, 0);
    // yq = Y @ Yq_w^T + b   : M=8192, N=512, K=1024
    gemm_tn_bias<<<dim3(HD / 64, (YLEN * BSZ) / 64), 256>>>(
        Y, YD, Yq_w, YD, yq_p, HD, Yq_b, YD, 0);

    // logits + bias + mask  : per batch (1024 x 2048), K=512
    logits_kernel<<<dim3(XLEN / 64, YLEN / 64, BSZ), 256>>>(
        alignment, mask, align_w);

    // softmax over x
    softmax_kernel<<<BSZ * YLEN, 256>>>();

    // attn_feat = attn @ xv : per batch (1024 x 512), K=2048
    attnfeat_kernel<<<dim3(HD / 64, YLEN / 64, BSZ), 256>>>();

    // out = Y @ Yw_w[:, :YD]^T + Yw_b
    gemm_tn_bias<<<dim3(YOUT / 64, (YLEN * BSZ) / 64), 256>>>(
        Y, YD, Yw_w, YD + HD, out, YOUT, Yw_b, YD, 0);
    // out += attn_feat @ Yw_w[:, YD:]^T
    gemm_tn_bias<<<dim3(YOUT / 64, (YLEN * BSZ) / 64), 256>>>(
        af_p, HD, Yw_w + YD, YD + HD, out, YOUT, (const float*)0, HD, 1);
}

// round 3
// speedup vs baseline: 2.6377x; 2.6377x over previous
#include <cuda_runtime.h>
#include <cuda_bf16.h>
#include <math.h>
#include <stdint.h>

#define XLEN 2048
#define YLEN 1024
#define BSZ  8
#define XD   1024
#define YD   1024
#define HD   512
#define YOUT 1024
#define CATD (YD + HD)
#define FMAXV 3.402823466e38f
#define INV_SQRT_HD 0.04419417382415922f

// ===================== PTX helpers (sm_80-compatible) =====================
__device__ __forceinline__ uint32_t smem_u32(const void* p) {
    uint32_t a;
    asm("{ .reg .u64 t; cvta.to.shared.u64 t, %1; cvt.u32.u64 %0, t; }" : "=r"(a) : "l"(p));
    return a;
}
#define CP16(dst, src) \
    asm volatile("cp.async.cg.shared.global [%0], [%1], 16;" :: "r"(dst), "l"(src))
#define CP_COMMIT() asm volatile("cp.async.commit_group;")
#define CP_WAIT1()  asm volatile("cp.async.wait_group 1;")

#define LDSM4(r, a) \
    asm volatile("ldmatrix.sync.aligned.m8n8.x4.shared.b16 {%0,%1,%2,%3}, [%4];" \
        : "=r"((r)[0]), "=r"((r)[1]), "=r"((r)[2]), "=r"((r)[3]) : "r"(a))

#define MMA_BF16(d, a, b0v, b1v) \
    asm volatile("mma.sync.aligned.m16n8k16.row.col.f32.bf16.bf16.f32 " \
        "{%0,%1,%2,%3}, {%4,%5,%6,%7}, {%8,%9}, {%0,%1,%2,%3};" \
        : "+f"((d)[0]), "+f"((d)[1]), "+f"((d)[2]), "+f"((d)[3]) \
        : "r"((a)[0]), "r"((a)[1]), "r"((a)[2]), "r"((a)[3]), "r"(b0v), "r"(b1v))

// SMEM tile: 128 rows x 32 bf16 (64B/row, 4 x 16B chunks). Swizzle keeps the
// 8 row-addresses of each ldmatrix phase on distinct 16B bank groups.
__device__ __forceinline__ uint32_t swz(int row, int chunk) {
    return (uint32_t)(row * 64 + ((chunk ^ ((row >> 1) & 3)) << 4));
}

// ===================== scratch (device globals) ==========================
#define AL __align__(16)
__device__ AL __nv_bfloat16 g_Xhi[XLEN * BSZ * XD],  g_Xlo[XLEN * BSZ * XD];
__device__ AL __nv_bfloat16 g_cat_hi[YLEN * BSZ * CATD], g_cat_lo[YLEN * BSZ * CATD];
__device__ AL __nv_bfloat16 g_Xkw_hi[HD * XD], g_Xkw_lo[HD * XD];
__device__ AL __nv_bfloat16 g_Xvw_hi[HD * XD], g_Xvw_lo[HD * XD];
__device__ AL __nv_bfloat16 g_Yqw_hi[HD * YD], g_Yqw_lo[HD * YD];
__device__ AL __nv_bfloat16 g_Yww_hi[YOUT * CATD], g_Yww_lo[YOUT * CATD];
__device__ AL __nv_bfloat16 g_xk_hi[XLEN * BSZ * HD], g_xk_lo[XLEN * BSZ * HD];
__device__ AL __nv_bfloat16 g_xv_hi[XLEN * BSZ * HD], g_xv_lo[XLEN * BSZ * HD];
__device__ AL __nv_bfloat16 g_yq_hi[YLEN * BSZ * HD], g_yq_lo[YLEN * BSZ * HD];
__device__ AL __nv_bfloat16 g_xvT_hi[BSZ * HD * XLEN], g_xvT_lo[BSZ * HD * XLEN];
__device__ AL float         g_logits[BSZ * YLEN * XLEN];
__device__ AL __nv_bfloat16 g_attn_hi[BSZ * YLEN * XLEN], g_attn_lo[BSZ * YLEN * XLEN];

// ===================== split fp32 -> bf16 hi/lo ==========================
__global__ __launch_bounds__(256) void split_kernel(
    const float* __restrict__ in, __nv_bfloat16* __restrict__ hi,
    __nv_bfloat16* __restrict__ lo, int incols, int outld, long n4)
{
    long i4 = (long)blockIdx.x * 256 + threadIdx.x;
    if (i4 >= n4) return;
    long base = i4 * 4;
    long r = base / incols, c = base - r * incols;
    float4 v = *(const float4*)(in + base);
    __nv_bfloat16 h0 = __float2bfloat16(v.x), h1 = __float2bfloat16(v.y),
                  h2 = __float2bfloat16(v.z), h3 = __float2bfloat16(v.w);
    __nv_bfloat16 l0 = __float2bfloat16(v.x - __bfloat162float(h0));
    __nv_bfloat16 l1 = __float2bfloat16(v.y - __bfloat162float(h1));
    __nv_bfloat16 l2 = __float2bfloat16(v.z - __bfloat162float(h2));
    __nv_bfloat16 l3 = __float2bfloat16(v.w - __bfloat162float(h3));
    long off = r * outld + c;
    __nv_bfloat162 hp0 = {h0, h1}, hp1 = {h2, h3}, lp0 = {l0, l1}, lp1 = {l2, l3};
    *(uint2*)(hi + off) = make_uint2(*(uint32_t*)&hp0, *(uint32_t*)&hp1);
    *(uint2*)(lo + off) = make_uint2(*(uint32_t*)&lp0, *(uint32_t*)&lp1);
}

// ===================== transpose xv (x*b,h) -> (b,h,x) ===================
__global__ __launch_bounds__(256) void transpose_xv()
{
    __shared__ __nv_bfloat16 th[32][33], tl[32][33];
    int b = blockIdx.z;
    int x0 = blockIdx.x * 32, h0 = blockIdx.y * 32;
    int tx = threadIdx.x, ty = threadIdx.y;
#pragma unroll
    for (int i = ty; i < 32; i += 8) {
        long src = ((long)(x0 + i) * BSZ + b) * HD + h0 + tx;
        th[i][tx] = g_xv_hi[src];
        tl[i][tx] = g_xv_lo[src];
    }
    __syncthreads();
#pragma unroll
    for (int i = ty; i < 32; i += 8) {
        long dst = (long)b * HD * XLEN + (long)(h0 + i) * XLEN + x0 + tx;
        g_xvT_hi[dst] = th[tx][i];
        g_xvT_lo[dst] = tl[tx][i];
    }
}

// ===================== softmax: fp32 logits -> bf16 hi/lo attn ===========
__global__ __launch_bounds__(256) void softmax_kernel()
{
    const long row = blockIdx.x;
    const float* p = g_logits + row * XLEN;
    __nv_bfloat16* ah = g_attn_hi + row * XLEN;
    __nv_bfloat16* al = g_attn_lo + row * XLEN;
    const int tid = threadIdx.x;

    float v[8];
    float mx = -FMAXV;
#pragma unroll
    for (int i = 0; i < 8; i++) { v[i] = p[tid + (i << 8)]; mx = fmaxf(mx, v[i]); }

    __shared__ float sred[8];
#pragma unroll
    for (int o = 16; o > 0; o >>= 1) mx = fmaxf(mx, __shfl_xor_sync(0xffffffff, mx, o));
    if ((tid & 31) == 0) sred[tid >> 5] = mx;
    __syncthreads();
    mx = sred[0];
#pragma unroll
    for (int w = 1; w < 8; w++) mx = fmaxf(mx, sred[w]);
    __syncthreads();

    float s = 0.0f;
#pragma unroll
    for (int i = 0; i < 8; i++) { v[i] = expf(v[i] - mx); s += v[i]; }
#pragma unroll
    for (int o = 16; o > 0; o >>= 1) s += __shfl_xor_sync(0xffffffff, s, o);
    if ((tid & 31) == 0) sred[tid >> 5] = s;
    __syncthreads();
    s = 0.0f;
#pragma unroll
    for (int w = 0; w < 8; w++) s += sred[w];

    const float inv = 1.0f / s;
#pragma unroll
    for (int i = 0; i < 8; i++) {
        float a = v[i] * inv;
        __nv_bfloat16 h = __float2bfloat16(a);
        __nv_bfloat16 l = __float2bfloat16(a - __bfloat162float(h));
        ah[tid + (i << 8)] = h;
        al[tid + (i << 8)] = l;
    }
}

// ===================== mma.sync bf16x3 GEMM ==============================
// C[M,N] = (Ahi+Alo)[M,K] @ (Bhi+Blo)[N,K]^T
// Block 128x128, BK=32, 8 warps (2x4), warp tile 64x32, 3-stage cp.async.
// MODE 0: +bias(optional) -> bf16 hi/lo;  MODE 1: logits epilogue -> fp32;
// MODE 2: +bias -> fp32.
struct GemmArgs {
    const __nv_bfloat16 *Ahi, *Alo, *Bhi, *Blo;
    long lda, ldb, Abatch, Bbatch;
    int K;
    float* Cf;
    __nv_bfloat16 *Chi, *Clo;
    long ldc, Cbatch;
    const float* bias;
    const float* align;
    const int*   mask;
    const float* alignw;
};

#define STG   32768            // Ahi 8K | Alo 8K | Bhi 8K | Blo 8K
#define NSTG  3
#define SMEM_BYTES (NSTG * STG)

template <int MODE>
__global__ __launch_bounds__(256, 1) void mma_gemm(GemmArgs g)
{
    extern __shared__ char smem[];
    const uint32_t sb = smem_u32(smem);
    const int tid = threadIdx.x, wid = tid >> 5, lane = tid & 31;
    const int b = blockIdx.z;
    const long m0 = (long)blockIdx.y * 128, n0 = (long)blockIdx.x * 128;
    const int wm = (wid >> 2) * 64;       // warp m offset
    const int wn = (wid & 3) * 32;        // warp n offset

    const __nv_bfloat16* Ahi = g.Ahi + (long)b * g.Abatch;
    const __nv_bfloat16* Alo = g.Alo + (long)b * g.Abatch;
    const __nv_bfloat16* Bhi = g.Bhi + (long)b * g.Bbatch;
    const __nv_bfloat16* Blo = g.Blo + (long)b * g.Bbatch;

    // ---- global->shared load plan: 2 rows per thread per tensor ----
    const int lrow = tid >> 2;          // 0..63
    const int lch  = tid & 3;
    uint32_t sw0 = swz(lrow, lch), sw1 = swz(lrow + 64, lch);
    const long ga0 = (m0 + lrow) * g.lda + lch * 8;
    const long ga1 = (m0 + lrow + 64) * g.lda + lch * 8;
    const long gb0 = (n0 + lrow) * g.ldb + lch * 8;
    const long gb1 = (n0 + lrow + 64) * g.ldb + lch * 8;

    const int NT = g.K >> 5;

    // ---- ldmatrix shared addresses (stage-relative) ----
    // A x4: lanes 0-15 rows r0+(lane&15) chunk kc; lanes 16-31 same rows chunk kc+1
    const int a_r = (lane & 15), a_c = (lane >> 4);
    // B x4: rows nb*16 + (lane&7) + ((lane>>4)&1)*8 ; chunk kc + ((lane>>3)&1)
    const int b_r = (lane & 7) + ((lane >> 4) & 1) * 8, b_c = (lane >> 3) & 1;

    float acc[4][4][4];
#pragma unroll
    for (int i = 0; i < 4; i++)
#pragma unroll
        for (int j = 0; j < 4; j++)
#pragma unroll
            for (int k = 0; k < 4; k++) acc[i][j][k] = 0.0f;

    auto load_stage = [&](int s, int it) {
        const long k0 = (long)it << 5;
        const uint32_t base = sb + s * STG;
        CP16(base + sw0,         (const char*)(Ahi + ga0 + k0));
        CP16(base + sw1,         (const char*)(Ahi + ga1 + k0));
        CP16(base + 8192  + sw0, (const char*)(Alo + ga0 + k0));
        CP16(base + 8192  + sw1, (const char*)(Alo + ga1 + k0));
        CP16(base + 16384 + sw0, (const char*)(Bhi + gb0 + k0));
        CP16(base + 16384 + sw1, (const char*)(Bhi + gb1 + k0));
        CP16(base + 24576 + sw0, (const char*)(Blo + gb0 + k0));
        CP16(base + 24576 + sw1, (const char*)(Blo + gb1 + k0));
        CP_COMMIT();
    };

    load_stage(0, 0);
    load_stage(1, 1);

    for (int it = 0; it < NT; ++it) {
        CP_WAIT1();
        __syncthreads();
        if (it + 2 < NT) load_stage((it + 2) % NSTG, it + 2);
        else CP_COMMIT();   // keep group accounting aligned

        const uint32_t st = sb + (it % NSTG) * STG;
#pragma unroll
        for (int ks = 0; ks < 2; ks++) {
            const int kc = ks * 2;
            uint32_t ah[4][4], al2[4][4], bh[2][4], bl[2][4];
#pragma unroll
            for (int mi = 0; mi < 4; mi++) {
                const uint32_t ao = swz(wm + mi * 16 + a_r, kc + a_c);
                LDSM4(ah[mi],  st + ao);
                LDSM4(al2[mi], st + 8192 + ao);
            }
#pragma unroll
            for (int nb = 0; nb < 2; nb++) {
                const uint32_t bo = swz(wn + nb * 16 + b_r, kc + b_c);
                LDSM4(bh[nb], st + 16384 + bo);
                LDSM4(bl[nb], st + 24576 + bo);
            }
#pragma unroll
            for (int mi = 0; mi < 4; mi++)
#pragma unroll
                for (int ni = 0; ni < 4; ni++) {
                    const int nb = ni >> 1, sub = (ni & 1) * 2;
                    MMA_BF16(acc[mi][ni], ah[mi],  bh[nb][sub], bh[nb][sub + 1]);
                    MMA_BF16(acc[mi][ni], ah[mi],  bl[nb][sub], bl[nb][sub + 1]);
                    MMA_BF16(acc[mi][ni], al2[mi], bh[nb][sub], bh[nb][sub + 1]);
                }
        }
        __syncthreads();
    }

    // ===================== epilogue =====================
    const float sig = (MODE == 1) ? (1.0f / (1.0f + expf(-__ldg(g.alignw)))) : 0.0f;

#pragma unroll
    for (int mi = 0; mi < 4; mi++) {
#pragma unroll
        for (int ni = 0; ni < 4; ni++) {
#pragma unroll
            for (int h = 0; h < 2; h++) {
                const long row = m0 + wm + mi * 16 + (lane >> 2) + h * 8;
                const long col = n0 + wn + ni * 8 + (lane & 3) * 2;
                float v0 = acc[mi][ni][h * 2 + 0];
                float v1 = acc[mi][ni][h * 2 + 1];
                const long idx = (long)b * g.Cbatch + row * g.ldc + col;
                if (MODE == 0) {
                    if (g.bias) { v0 += g.bias[col]; v1 += g.bias[col + 1]; }
                    __nv_bfloat16 h0 = __float2bfloat16(v0), h1 = __float2bfloat16(v1);
                    __nv_bfloat16 l0 = __float2bfloat16(v0 - __bfloat162float(h0));
                    __nv_bfloat16 l1 = __float2bfloat16(v1 - __bfloat162float(h1));
                    __nv_bfloat162 hh = {h0, h1}, ll = {l0, l1};
                    *(uint32_t*)(g.Chi + idx) = *(uint32_t*)&hh;
                    *(uint32_t*)(g.Clo + idx) = *(uint32_t*)&ll;
                } else if (MODE == 1) {
                    float2 av = *(const float2*)(g.align + idx);
                    int2 mv = *(const int2*)(g.mask + idx);
                    float o0 = v0 * INV_SQRT_HD + sig * av.x;
                    float o1 = v1 * INV_SQRT_HD + sig * av.y;
                    o0 = fmaxf(o0, -FMAXV);
                    o1 = fmaxf(o1, -FMAXV);
                    if (mv.x != 0) o0 = fmaxf(o0 - FMAXV, -FMAXV);
                    if (mv.y != 0) o1 = fmaxf(o1 - FMAXV, -FMAXV);
                    *(float2*)(g.Cf + idx) = make_float2(o0, o1);
                } else {
                    v0 += g.bias[col];
                    v1 += g.bias[col + 1];
                    *(float2*)(g.Cf + idx) = make_float2(v0, v1);
                }
            }
        }
    }
}

// ===================== launch ============================================
extern "C" void kernel_launch(void* const* d_in, const int* in_sizes, int n_in,
                              void* d_out, int out_size)
{
    const float* X         = (const float*)d_in[0];
    const float* Y         = (const float*)d_in[1];
    const float* alignment = (const float*)d_in[2];
    const int*   mask      = (const int*)d_in[3];
    const float* Xk_w      = (const float*)d_in[4];
    const float* Xk_b      = (const float*)d_in[5];
    const float* Xv_w      = (const float*)d_in[6];
    const float* Xv_b      = (const float*)d_in[7];
    const float* Yq_w      = (const float*)d_in[8];
    const float* Yq_b      = (const float*)d_in[9];
    const float* Yw_w      = (const float*)d_in[10];
    const float* Yw_b      = (const float*)d_in[11];
    const float* align_w   = (const float*)d_in[12];
    float* out = (float*)d_out;

    cudaFuncSetAttribute(mma_gemm<0>, cudaFuncAttributeMaxDynamicSharedMemorySize, SMEM_BYTES);
    cudaFuncSetAttribute(mma_gemm<1>, cudaFuncAttributeMaxDynamicSharedMemorySize, SMEM_BYTES);
    cudaFuncSetAttribute(mma_gemm<2>, cudaFuncAttributeMaxDynamicSharedMemorySize, SMEM_BYTES);

#define SYM(p, s) do { void* _t; cudaGetSymbolAddress(&_t, s); p = (decltype(p))_t; } while (0)
    __nv_bfloat16 *Xhi, *Xlo, *cat_hi, *cat_lo, *Xkw_hi, *Xkw_lo, *Xvw_hi, *Xvw_lo,
        *Yqw_hi, *Yqw_lo, *Yww_hi, *Yww_lo, *xk_hi, *xk_lo, *xv_hi, *xv_lo,
        *yq_hi, *yq_lo, *xvT_hi, *xvT_lo, *attn_hi, *attn_lo;
    float* logits;
    SYM(Xhi, g_Xhi); SYM(Xlo, g_Xlo); SYM(cat_hi, g_cat_hi); SYM(cat_lo, g_cat_lo);
    SYM(Xkw_hi, g_Xkw_hi); SYM(Xkw_lo, g_Xkw_lo); SYM(Xvw_hi, g_Xvw_hi); SYM(Xvw_lo, g_Xvw_lo);
    SYM(Yqw_hi, g_Yqw_hi); SYM(Yqw_lo, g_Yqw_lo); SYM(Yww_hi, g_Yww_hi); SYM(Yww_lo, g_Yww_lo);
    SYM(xk_hi, g_xk_hi); SYM(xk_lo, g_xk_lo); SYM(xv_hi, g_xv_hi); SYM(xv_lo, g_xv_lo);
    SYM(yq_hi, g_yq_hi); SYM(yq_lo, g_yq_lo); SYM(xvT_hi, g_xvT_hi); SYM(xvT_lo, g_xvT_lo);
    SYM(attn_hi, g_attn_hi); SYM(attn_lo, g_attn_lo); SYM(logits, g_logits);

    auto split = [&](const float* in, __nv_bfloat16* hi, __nv_bfloat16* lo,
                     int incols, int outld, long nelem) {
        long n4 = nelem / 4;
        split_kernel<<<(unsigned)((n4 + 255) / 256), 256>>>(in, hi, lo, incols, outld, n4);
    };
    split(X, Xhi, Xlo, XD, XD, (long)XLEN * BSZ * XD);
    split(Y, cat_hi, cat_lo, YD, CATD, (long)YLEN * BSZ * YD);
    split(Xk_w, Xkw_hi, Xkw_lo, XD, XD, (long)HD * XD);
    split(Xv_w, Xvw_hi, Xvw_lo, XD, XD, (long)HD * XD);
    split(Yq_w, Yqw_hi, Yqw_lo, YD, YD, (long)HD * YD);
    split(Yw_w, Yww_hi, Yww_lo, CATD, CATD, (long)YOUT * CATD);

    GemmArgs a = {};

    // ---- xk = X @ Xk_w^T + b : M=16384 N=512 K=1024 ----
    a.Ahi = Xhi; a.Alo = Xlo; a.lda = XD; a.Abatch = 0;
    a.Bhi = Xkw_hi; a.Blo = Xkw_lo; a.ldb = XD; a.Bbatch = 0;
    a.K = XD; a.Chi = xk_hi; a.Clo = xk_lo; a.ldc = HD; a.Cbatch = 0; a.bias = Xk_b;
    mma_gemm<0><<<dim3(HD / 128, XLEN * BSZ / 128, 1), 256, SMEM_BYTES>>>(a);

    // ---- xv = X @ Xv_w^T + b ----
    a.Bhi = Xvw_hi; a.Blo = Xvw_lo; a.Chi = xv_hi; a.Clo = xv_lo; a.bias = Xv_b;
    mma_gemm<0><<<dim3(HD / 128, XLEN * BSZ / 128, 1), 256, SMEM_BYTES>>>(a);

    // ---- yq = Y @ Yq_w^T + b : M=8192 N=512 K=1024 ----
    a.Ahi = cat_hi; a.Alo = cat_lo; a.lda = CATD;
    a.Bhi = Yqw_hi; a.Blo = Yqw_lo; a.ldb = YD;
    a.Chi = yq_hi; a.Clo = yq_lo; a.bias = Yq_b;
    mma_gemm<0><<<dim3(HD / 128, YLEN * BSZ / 128, 1), 256, SMEM_BYTES>>>(a);

    // ---- transpose xv -> (b,h,x) ----
    transpose_xv<<<dim3(XLEN / 32, HD / 32, BSZ), dim3(32, 8)>>>();

    // ---- logits[b,y,x] : per batch M=1024 N=2048 K=512, fused epilogue ----
    a = {};
    a.Ahi = yq_hi; a.Alo = yq_lo; a.lda = BSZ * HD; a.Abatch = HD;
    a.Bhi = xk_hi; a.Blo = xk_lo; a.ldb = BSZ * HD; a.Bbatch = HD;
    a.K = HD; a.Cf = logits; a.ldc = XLEN; a.Cbatch = (long)YLEN * XLEN;
    a.align = alignment; a.mask = mask; a.alignw = align_w;
    mma_gemm<1><<<dim3(XLEN / 128, YLEN / 128, BSZ), 256, SMEM_BYTES>>>(a);

    // ---- softmax -> attn hi/lo ----
    softmax_kernel<<<BSZ * YLEN, 256>>>();

    // ---- attn_feat = attn @ xvT^T -> cat[:, 1024:1536] : per batch M=1024 N=512 K=2048 ----
    a = {};
    a.Ahi = attn_hi; a.Alo = attn_lo; a.lda = XLEN; a.Abatch = (long)YLEN * XLEN;
    a.Bhi = xvT_hi; a.Blo = xvT_lo; a.ldb = XLEN; a.Bbatch = (long)HD * XLEN;
    a.K = XLEN; a.Chi = cat_hi + YD; a.Clo = cat_lo + YD;
    a.ldc = (long)BSZ * CATD; a.Cbatch = CATD; a.bias = nullptr;
    mma_gemm<0><<<dim3(HD / 128, YLEN / 128, BSZ), 256, SMEM_BYTES>>>(a);

    // ---- out = cat @ Yw_w^T + b : M=8192 N=1024 K=1536 ----
    a = {};
    a.Ahi = cat_hi; a.Alo = cat_lo; a.lda = CATD; a.Abatch = 0;
    a.Bhi = Yww_hi; a.Blo = Yww_lo; a.ldb = CATD; a.Bbatch = 0;
    a.K = CATD; a.Cf = out; a.ldc = YOUT; a.Cbatch = 0; a.bias = Yw_b;
    mma_gemm<2><<<dim3(YOUT / 128, YLEN * BSZ / 128, 1), 256, SMEM_BYTES>>>(a);
}

// round 4
// speedup vs baseline: 3.3228x; 1.2597x over previous
#include <cuda_runtime.h>
#include <cuda_fp16.h>
#include <math.h>
#include <stdint.h>

#define XLEN 2048
#define YLEN 1024
#define BSZ  8
#define XD   1024
#define YD   1024
#define HD   512
#define YOUT 1024
#define CATD (YD + HD)
#define FMAXV 3.402823466e38f
#define INV_SQRT_HD 0.04419417382415922f

// ===================== PTX helpers =====================
__device__ __forceinline__ uint32_t smem_u32(const void* p) {
    uint32_t a;
    asm("{ .reg .u64 t; cvta.to.shared.u64 t, %1; cvt.u32.u64 %0, t; }" : "=r"(a) : "l"(p));
    return a;
}
#define CP16(dst, src) \
    asm volatile("cp.async.cg.shared.global [%0], [%1], 16;" :: "r"(dst), "l"(src))
#define CP_COMMIT() asm volatile("cp.async.commit_group;")
#define CP_WAIT2()  asm volatile("cp.async.wait_group 2;")

#define LDSM4(r, a) \
    asm volatile("ldmatrix.sync.aligned.m8n8.x4.shared.b16 {%0,%1,%2,%3}, [%4];" \
        : "=r"((r)[0]), "=r"((r)[1]), "=r"((r)[2]), "=r"((r)[3]) : "r"(a))

#define MMA_F16(d, a, b0v, b1v) \
    asm volatile("mma.sync.aligned.m16n8k16.row.col.f32.f16.f16.f32 " \
        "{%0,%1,%2,%3}, {%4,%5,%6,%7}, {%8,%9}, {%0,%1,%2,%3};" \
        : "+f"((d)[0]), "+f"((d)[1]), "+f"((d)[2]), "+f"((d)[3]) \
        : "r"((a)[0]), "r"((a)[1]), "r"((a)[2]), "r"((a)[3]), "r"(b0v), "r"(b1v))

// SMEM tile: 128 rows x 32 f16 (64B/row, 4 x 16B chunks), bank-conflict swizzle.
__device__ __forceinline__ uint32_t swz(int row, int chunk) {
    return (uint32_t)(row * 64 + ((chunk ^ ((row >> 1) & 3)) << 4));
}

// ===================== scratch (device globals) ==========================
#define AL __align__(16)
__device__ AL __half g_Xhi[XLEN * BSZ * XD];
__device__ AL __half g_cat_hi[YLEN * BSZ * CATD];
__device__ AL __half g_Xkw_hi[HD * XD],  g_Xkw_lo[HD * XD];
__device__ AL __half g_Xvw_hi[HD * XD],  g_Xvw_lo[HD * XD];
__device__ AL __half g_Yqw_hi[HD * YD],  g_Yqw_lo[HD * YD];
__device__ AL __half g_Yww_hi[YOUT * CATD], g_Yww_lo[YOUT * CATD];
__device__ AL __half g_xk_hi[XLEN * BSZ * HD], g_xk_lo[XLEN * BSZ * HD];
__device__ AL __half g_xv_hi[XLEN * BSZ * HD], g_xv_lo[XLEN * BSZ * HD];
__device__ AL __half g_yq_hi[YLEN * BSZ * HD];
__device__ AL __half g_xvT_hi[BSZ * HD * XLEN], g_xvT_lo[BSZ * HD * XLEN];
__device__ AL float  g_logits[BSZ * YLEN * XLEN];
__device__ AL __half g_attn_hi[BSZ * YLEN * XLEN];

// ===================== fused split: fp32 -> fp16 (hi [, lo]) =============
struct SplitArgs {
    const float* src[6];
    __half* hi[6];
    __half* lo[6];       // null -> hi only
    int incols[6], outld[6];
    long n4[6];
};

__global__ __launch_bounds__(256) void split_all(SplitArgs s)
{
    const int e = blockIdx.y;
    long i4 = (long)blockIdx.x * 256 + threadIdx.x;
    if (i4 >= s.n4[e]) return;
    long base = i4 * 4;
    long r = base / s.incols[e], c = base - r * s.incols[e];
    float4 v = *(const float4*)(s.src[e] + base);
    __half h0 = __float2half_rn(v.x), h1 = __float2half_rn(v.y),
           h2 = __float2half_rn(v.z), h3 = __float2half_rn(v.w);
    long off = r * s.outld[e] + c;
    __half2 hp0 = {h0, h1}, hp1 = {h2, h3};
    *(uint2*)(s.hi[e] + off) = make_uint2(*(uint32_t*)&hp0, *(uint32_t*)&hp1);
    if (s.lo[e]) {
        __half l0 = __float2half_rn(v.x - __half2float(h0));
        __half l1 = __float2half_rn(v.y - __half2float(h1));
        __half l2 = __float2half_rn(v.z - __half2float(h2));
        __half l3 = __float2half_rn(v.w - __half2float(h3));
        __half2 lp0 = {l0, l1}, lp1 = {l2, l3};
        *(uint2*)(s.lo[e] + off) = make_uint2(*(uint32_t*)&lp0, *(uint32_t*)&lp1);
    }
}

// ===================== transpose xv (x*b,h) -> (b,h,x) ===================
__global__ __launch_bounds__(256) void transpose_xv()
{
    __shared__ __half th[32][33], tl[32][33];
    int b = blockIdx.z;
    int x0 = blockIdx.x * 32, h0 = blockIdx.y * 32;
    int tx = threadIdx.x, ty = threadIdx.y;
#pragma unroll
    for (int i = ty; i < 32; i += 8) {
        long src = ((long)(x0 + i) * BSZ + b) * HD + h0 + tx;
        th[i][tx] = g_xv_hi[src];
        tl[i][tx] = g_xv_lo[src];
    }
    __syncthreads();
#pragma unroll
    for (int i = ty; i < 32; i += 8) {
        long dst = (long)b * HD * XLEN + (long)(h0 + i) * XLEN + x0 + tx;
        g_xvT_hi[dst] = th[tx][i];
        g_xvT_lo[dst] = tl[tx][i];
    }
}

// ===================== softmax: fp32 logits -> fp16 attn =================
__global__ __launch_bounds__(256) void softmax_kernel()
{
    const long row = blockIdx.x;
    const float* p = g_logits + row * XLEN;
    __half* ah = g_attn_hi + row * XLEN;
    const int tid = threadIdx.x;

    float v[8];
    float mx = -FMAXV;
#pragma unroll
    for (int i = 0; i < 8; i++) { v[i] = p[tid + (i << 8)]; mx = fmaxf(mx, v[i]); }

    __shared__ float sred[8];
#pragma unroll
    for (int o = 16; o > 0; o >>= 1) mx = fmaxf(mx, __shfl_xor_sync(0xffffffff, mx, o));
    if ((tid & 31) == 0) sred[tid >> 5] = mx;
    __syncthreads();
    mx = sred[0];
#pragma unroll
    for (int w = 1; w < 8; w++) mx = fmaxf(mx, sred[w]);
    __syncthreads();

    float s = 0.0f;
#pragma unroll
    for (int i = 0; i < 8; i++) { v[i] = expf(v[i] - mx); s += v[i]; }
#pragma unroll
    for (int o = 16; o > 0; o >>= 1) s += __shfl_xor_sync(0xffffffff, s, o);
    if ((tid & 31) == 0) sred[tid >> 5] = s;
    __syncthreads();
    s = 0.0f;
#pragma unroll
    for (int w = 0; w < 8; w++) s += sred[w];

    const float inv = 1.0f / s;
#pragma unroll
    for (int i = 0; i < 8; i++)
        ah[tid + (i << 8)] = __float2half_rn(v[i] * inv);
}

// ===================== fp16 2-term GEMM ==================================
// C[M,N] = Ah[M,K] @ (Bh+Bl)[N,K]^T  (A rounded to fp16, B split hi/lo)
// Block 128x128, BK=32, 8 warps (2x4), warp tile 64x32, 4-stage cp.async.
// MODE 0: v=(acc+bias)*scale -> fp16 hi (+lo if Clo);  MODE 1: logits
// epilogue -> fp32;  MODE 2: acc+bias -> fp32.
struct GemmArgs {
    const __half *Ah, *Bh, *Bl;
    long lda, ldb, Abatch, Bbatch;
    int K;
    float* Cf;
    __half *Chi, *Clo;
    long ldc, Cbatch;
    const float* bias;
    float scale;
    const float* align;
    const int*   mask;
    const float* alignw;
};

#define STG   24576            // Ah 8K | Bh 8K | Bl 8K
#define NSTG  4
#define SMEM_BYTES (NSTG * STG)

template <int MODE>
__global__ __launch_bounds__(256, 1) void mma_gemm(GemmArgs g)
{
    extern __shared__ char smem[];
    const uint32_t sb = smem_u32(smem);
    const int tid = threadIdx.x, wid = tid >> 5, lane = tid & 31;
    const int b = blockIdx.z;
    const long m0 = (long)blockIdx.y * 128, n0 = (long)blockIdx.x * 128;
    const int wm = (wid >> 2) * 64;
    const int wn = (wid & 3) * 32;

    const __half* Ah = g.Ah + (long)b * g.Abatch;
    const __half* Bh = g.Bh + (long)b * g.Bbatch;
    const __half* Bl = g.Bl + (long)b * g.Bbatch;

    // global->shared plan: 2 x 16B chunks per thread per tensor
    const int r0c = tid >> 2,        ch0 = tid & 3;          // chunk id tid
    const int r1c = (tid + 256) >> 2, ch1 = (tid + 256) & 3; // chunk id tid+256
    const uint32_t swA0 = swz(r0c, ch0), swA1 = swz(r1c, ch1);
    const long ga0 = (m0 + r0c) * g.lda + ch0 * 8;
    const long ga1 = (m0 + r1c) * g.lda + ch1 * 8;
    const long gb0 = (n0 + r0c) * g.ldb + ch0 * 8;
    const long gb1 = (n0 + r1c) * g.ldb + ch1 * 8;

    const int NT = g.K >> 5;

    // ldmatrix addressing
    const int a_r = (lane & 15), a_c = (lane >> 4);
    const int b_r = (lane & 7) + ((lane >> 4) & 1) * 8, b_c = (lane >> 3) & 1;

    float acc[4][4][4];
#pragma unroll
    for (int i = 0; i < 4; i++)
#pragma unroll
        for (int j = 0; j < 4; j++)
#pragma unroll
            for (int k = 0; k < 4; k++) acc[i][j][k] = 0.0f;

    auto load_stage = [&](int s, int it) {
        const long k0 = (long)it << 5;
        const uint32_t base = sb + s * STG;
        CP16(base + swA0,         (const char*)(Ah + ga0 + k0));
        CP16(base + swA1,         (const char*)(Ah + ga1 + k0));
        CP16(base + 8192  + swA0, (const char*)(Bh + gb0 + k0));
        CP16(base + 8192  + swA1, (const char*)(Bh + gb1 + k0));
        CP16(base + 16384 + swA0, (const char*)(Bl + gb0 + k0));
        CP16(base + 16384 + swA1, (const char*)(Bl + gb1 + k0));
        CP_COMMIT();
    };

    load_stage(0, 0);
    load_stage(1, 1);
    load_stage(2, 2);

    for (int it = 0; it < NT; ++it) {
        CP_WAIT2();
        __syncthreads();
        if (it + 3 < NT) load_stage((it + 3) & 3, it + 3);
        else CP_COMMIT();

        const uint32_t st = sb + (it & 3) * STG;
#pragma unroll
        for (int ks = 0; ks < 2; ks++) {
            const int kc = ks * 2;
            uint32_t ah[4][4], bh[2][4], bl[2][4];
#pragma unroll
            for (int mi = 0; mi < 4; mi++) {
                const uint32_t ao = swz(wm + mi * 16 + a_r, kc + a_c);
                LDSM4(ah[mi], st + ao);
            }
#pragma unroll
            for (int nb = 0; nb < 2; nb++) {
                const uint32_t bo = swz(wn + nb * 16 + b_r, kc + b_c);
                LDSM4(bh[nb], st + 8192  + bo);
                LDSM4(bl[nb], st + 16384 + bo);
            }
#pragma unroll
            for (int mi = 0; mi < 4; mi++)
#pragma unroll
                for (int ni = 0; ni < 4; ni++) {
                    const int nb = ni >> 1, sub = (ni & 1) * 2;
                    MMA_F16(acc[mi][ni], ah[mi], bh[nb][sub], bh[nb][sub + 1]);
                    MMA_F16(acc[mi][ni], ah[mi], bl[nb][sub], bl[nb][sub + 1]);
                }
        }
        __syncthreads();
    }

    // ===================== epilogue =====================
    const float sig = (MODE == 1) ? (1.0f / (1.0f + expf(-__ldg(g.alignw)))) : 0.0f;

#pragma unroll
    for (int mi = 0; mi < 4; mi++) {
#pragma unroll
        for (int ni = 0; ni < 4; ni++) {
#pragma unroll
            for (int h = 0; h < 2; h++) {
                const long row = m0 + wm + mi * 16 + (lane >> 2) + h * 8;
                const long col = n0 + wn + ni * 8 + (lane & 3) * 2;
                float v0 = acc[mi][ni][h * 2 + 0];
                float v1 = acc[mi][ni][h * 2 + 1];
                const long idx = (long)b * g.Cbatch + row * g.ldc + col;
                if (MODE == 0) {
                    if (g.bias) { v0 += g.bias[col]; v1 += g.bias[col + 1]; }
                    v0 *= g.scale; v1 *= g.scale;
                    __half h0 = __float2half_rn(v0), h1 = __float2half_rn(v1);
                    __half2 hh = {h0, h1};
                    *(uint32_t*)(g.Chi + idx) = *(uint32_t*)&hh;
                    if (g.Clo) {
                        __half l0 = __float2half_rn(v0 - __half2float(h0));
                        __half l1 = __float2half_rn(v1 - __half2float(h1));
                        __half2 ll = {l0, l1};
                        *(uint32_t*)(g.Clo + idx) = *(uint32_t*)&ll;
                    }
                } else if (MODE == 1) {
                    float2 av = *(const float2*)(g.align + idx);
                    int2 mv = *(const int2*)(g.mask + idx);
                    float o0 = v0 + sig * av.x;
                    float o1 = v1 + sig * av.y;
                    o0 = fmaxf(o0, -FMAXV);
                    o1 = fmaxf(o1, -FMAXV);
                    if (mv.x != 0) o0 = fmaxf(o0 - FMAXV, -FMAXV);
                    if (mv.y != 0) o1 = fmaxf(o1 - FMAXV, -FMAXV);
                    *(float2*)(g.Cf + idx) = make_float2(o0, o1);
                } else {
                    v0 += g.bias[col];
                    v1 += g.bias[col + 1];
                    *(float2*)(g.Cf + idx) = make_float2(v0, v1);
                }
            }
        }
    }
}

// ===================== launch ============================================
extern "C" void kernel_launch(void* const* d_in, const int* in_sizes, int n_in,
                              void* d_out, int out_size)
{
    const float* X         = (const float*)d_in[0];
    const float* Y         = (const float*)d_in[1];
    const float* alignment = (const float*)d_in[2];
    const int*   mask      = (const int*)d_in[3];
    const float* Xk_w      = (const float*)d_in[4];
    const float* Xk_b      = (const float*)d_in[5];
    const float* Xv_w      = (const float*)d_in[6];
    const float* Xv_b      = (const float*)d_in[7];
    const float* Yq_w      = (const float*)d_in[8];
    const float* Yq_b      = (const float*)d_in[9];
    const float* Yw_w      = (const float*)d_in[10];
    const float* Yw_b      = (const float*)d_in[11];
    const float* align_w   = (const float*)d_in[12];
    float* out = (float*)d_out;

    cudaFuncSetAttribute(mma_gemm<0>, cudaFuncAttributeMaxDynamicSharedMemorySize, SMEM_BYTES);
    cudaFuncSetAttribute(mma_gemm<1>, cudaFuncAttributeMaxDynamicSharedMemorySize, SMEM_BYTES);
    cudaFuncSetAttribute(mma_gemm<2>, cudaFuncAttributeMaxDynamicSharedMemorySize, SMEM_BYTES);

#define SYM(p, s) do { void* _t; cudaGetSymbolAddress(&_t, s); p = (decltype(p))_t; } while (0)
    __half *Xhi, *cat_hi, *Xkw_hi, *Xkw_lo, *Xvw_hi, *Xvw_lo,
        *Yqw_hi, *Yqw_lo, *Yww_hi, *Yww_lo, *xk_hi, *xk_lo, *xv_hi, *xv_lo,
        *yq_hi, *xvT_hi, *xvT_lo, *attn_hi;
    float* logits;
    SYM(Xhi, g_Xhi); SYM(cat_hi, g_cat_hi);
    SYM(Xkw_hi, g_Xkw_hi); SYM(Xkw_lo, g_Xkw_lo); SYM(Xvw_hi, g_Xvw_hi); SYM(Xvw_lo, g_Xvw_lo);
    SYM(Yqw_hi, g_Yqw_hi); SYM(Yqw_lo, g_Yqw_lo); SYM(Yww_hi, g_Yww_hi); SYM(Yww_lo, g_Yww_lo);
    SYM(xk_hi, g_xk_hi); SYM(xk_lo, g_xk_lo); SYM(xv_hi, g_xv_hi); SYM(xv_lo, g_xv_lo);
    SYM(yq_hi, g_yq_hi); SYM(xvT_hi, g_xvT_hi); SYM(xvT_lo, g_xvT_lo);
    SYM(attn_hi, g_attn_hi); SYM(logits, g_logits);

    // ---- fused split (1 launch) ----
    SplitArgs sa;
    // 0: X (A-side, hi only)
    sa.src[0] = X;    sa.hi[0] = Xhi;    sa.lo[0] = nullptr;
    sa.incols[0] = XD;   sa.outld[0] = XD;   sa.n4[0] = (long)XLEN * BSZ * XD / 4;
    // 1: Y -> cat[:, :YD] (A-side, hi only)
    sa.src[1] = Y;    sa.hi[1] = cat_hi; sa.lo[1] = nullptr;
    sa.incols[1] = YD;   sa.outld[1] = CATD; sa.n4[1] = (long)YLEN * BSZ * YD / 4;
    // 2-5: weights (B-side, hi+lo)
    sa.src[2] = Xk_w; sa.hi[2] = Xkw_hi; sa.lo[2] = Xkw_lo;
    sa.incols[2] = XD;   sa.outld[2] = XD;   sa.n4[2] = (long)HD * XD / 4;
    sa.src[3] = Xv_w; sa.hi[3] = Xvw_hi; sa.lo[3] = Xvw_lo;
    sa.incols[3] = XD;   sa.outld[3] = XD;   sa.n4[3] = (long)HD * XD / 4;
    sa.src[4] = Yq_w; sa.hi[4] = Yqw_hi; sa.lo[4] = Yqw_lo;
    sa.incols[4] = YD;   sa.outld[4] = YD;   sa.n4[4] = (long)HD * YD / 4;
    sa.src[5] = Yw_w; sa.hi[5] = Yww_hi; sa.lo[5] = Yww_lo;
    sa.incols[5] = CATD; sa.outld[5] = CATD; sa.n4[5] = (long)YOUT * CATD / 4;
    long maxn4 = sa.n4[0];
    for (int i = 1; i < 6; i++) if (sa.n4[i] > maxn4) maxn4 = sa.n4[i];
    split_all<<<dim3((unsigned)((maxn4 + 255) / 256), 6), 256>>>(sa);

    GemmArgs a = {};

    // ---- xk = X @ Xk_w^T + b : M=16384 N=512 K=1024 (B-side out: hi+lo) ----
    a.Ah = Xhi; a.lda = XD; a.Abatch = 0;
    a.Bh = Xkw_hi; a.Bl = Xkw_lo; a.ldb = XD; a.Bbatch = 0;
    a.K = XD; a.Chi = xk_hi; a.Clo = xk_lo; a.ldc = HD; a.Cbatch = 0;
    a.bias = Xk_b; a.scale = 1.0f;
    mma_gemm<0><<<dim3(HD / 128, XLEN * BSZ / 128, 1), 256, SMEM_BYTES>>>(a);

    // ---- xv = X @ Xv_w^T + b (hi+lo) ----
    a.Bh = Xvw_hi; a.Bl = Xvw_lo; a.Chi = xv_hi; a.Clo = xv_lo; a.bias = Xv_b;
    mma_gemm<0><<<dim3(HD / 128, XLEN * BSZ / 128, 1), 256, SMEM_BYTES>>>(a);

    // ---- yq = (Y @ Yq_w^T + b) / sqrt(HD) : M=8192 N=512 K=1024 (hi only) ----
    a.Ah = cat_hi; a.lda = CATD;
    a.Bh = Yqw_hi; a.Bl = Yqw_lo; a.ldb = YD;
    a.Chi = yq_hi; a.Clo = nullptr; a.bias = Yq_b; a.scale = INV_SQRT_HD;
    mma_gemm<0><<<dim3(HD / 128, YLEN * BSZ / 128, 1), 256, SMEM_BYTES>>>(a);

    // ---- transpose xv -> (b,h,x) ----
    transpose_xv<<<dim3(XLEN / 32, HD / 32, BSZ), dim3(32, 8)>>>();

    // ---- logits[b,y,x] : per batch M=1024 N=2048 K=512 (launch #5 -> ncu) ----
    a = {};
    a.Ah = yq_hi; a.lda = BSZ * HD; a.Abatch = HD;
    a.Bh = xk_hi; a.Bl = xk_lo; a.ldb = BSZ * HD; a.Bbatch = HD;
    a.K = HD; a.Cf = logits; a.ldc = XLEN; a.Cbatch = (long)YLEN * XLEN;
    a.align = alignment; a.mask = mask; a.alignw = align_w; a.scale = 1.0f;
    mma_gemm<1><<<dim3(XLEN / 128, YLEN / 128, BSZ), 256, SMEM_BYTES>>>(a);

    // ---- softmax -> attn (hi only) ----
    softmax_kernel<<<BSZ * YLEN, 256>>>();

    // ---- attn_feat = attn @ xvT^T -> cat[:, 1024:1536] : per batch M=1024 N=512 K=2048 ----
    a = {};
    a.Ah = attn_hi; a.lda = XLEN; a.Abatch = (long)YLEN * XLEN;
    a.Bh = xvT_hi; a.Bl = xvT_lo; a.ldb = XLEN; a.Bbatch = (long)HD * XLEN;
    a.K = XLEN; a.Chi = cat_hi + YD; a.Clo = nullptr;
    a.ldc = (long)BSZ * CATD; a.Cbatch = CATD; a.bias = nullptr; a.scale = 1.0f;
    mma_gemm<0><<<dim3(HD / 128, YLEN / 128, BSZ), 256, SMEM_BYTES>>>(a);

    // ---- out = cat @ Yw_w^T + b : M=8192 N=1024 K=1536 ----
    a = {};
    a.Ah = cat_hi; a.lda = CATD; a.Abatch = 0;
    a.Bh = Yww_hi; a.Bl = Yww_lo; a.ldb = CATD; a.Bbatch = 0;
    a.K = CATD; a.Cf = out; a.ldc = YOUT; a.Cbatch = 0; a.bias = Yw_b; a.scale = 1.0f;
    mma_gemm<2><<<dim3(YOUT / 128, YLEN * BSZ / 128, 1), 256, SMEM_BYTES>>>(a);
}

// round 5
// speedup vs baseline: 4.1549x; 1.2504x over previous
#include <cuda_runtime.h>
#include <cuda_fp16.h>
#include <math.h>
#include <stdint.h>

#define XLEN 2048
#define YLEN 1024
#define BSZ  8
#define XD   1024
#define YD   1024
#define HD   512
#define YOUT 1024
#define CATD (YD + HD)
#define FMAXV 3.402823466e38f
#define INV_SQRT_HD 0.04419417382415922f

// ===================== PTX helpers =====================
__device__ __forceinline__ uint32_t smem_u32(const void* p) {
    uint32_t a;
    asm("{ .reg .u64 t; cvta.to.shared.u64 t, %1; cvt.u32.u64 %0, t; }" : "=r"(a) : "l"(p));
    return a;
}
#define CP16(dst, src) \
    asm volatile("cp.async.cg.shared.global [%0], [%1], 16;" :: "r"(dst), "l"(src))
#define CP_COMMIT() asm volatile("cp.async.commit_group;")
#define CP_WAIT1()  asm volatile("cp.async.wait_group 1;")

#define LDSM4(r, a) \
    asm volatile("ldmatrix.sync.aligned.m8n8.x4.shared.b16 {%0,%1,%2,%3}, [%4];" \
        : "=r"((r)[0]), "=r"((r)[1]), "=r"((r)[2]), "=r"((r)[3]) : "r"(a))

#define MMA_F16(d, a, b0v, b1v) \
    asm volatile("mma.sync.aligned.m16n8k16.row.col.f32.f16.f16.f32 " \
        "{%0,%1,%2,%3}, {%4,%5,%6,%7}, {%8,%9}, {%0,%1,%2,%3};" \
        : "+f"((d)[0]), "+f"((d)[1]), "+f"((d)[2]), "+f"((d)[3]) \
        : "r"((a)[0]), "r"((a)[1]), "r"((a)[2]), "r"((a)[3]), "r"(b0v), "r"(b1v))

// SMEM tile: 128 rows x 32 f16 (64B/row, 4 x 16B chunks), bank-conflict swizzle.
__device__ __forceinline__ uint32_t swz(int row, int chunk) {
    return (uint32_t)(row * 64 + ((chunk ^ ((row >> 1) & 3)) << 4));
}

// ===================== scratch (device globals) ==========================
#define AL __align__(16)
__device__ AL __half g_Xhi[XLEN * BSZ * XD];
__device__ AL __half g_cat_hi[YLEN * BSZ * CATD];
__device__ AL __half g_Xkw_hi[HD * XD],  g_Xkw_lo[HD * XD];
__device__ AL __half g_Xvw_hi[HD * XD],  g_Xvw_lo[HD * XD];
__device__ AL __half g_Yqw_hi[HD * YD],  g_Yqw_lo[HD * YD];
__device__ AL __half g_Yww_hi[YOUT * CATD], g_Yww_lo[YOUT * CATD];
__device__ AL __half g_xk_hi[XLEN * BSZ * HD], g_xk_lo[XLEN * BSZ * HD];
__device__ AL __half g_xv_hi[XLEN * BSZ * HD], g_xv_lo[XLEN * BSZ * HD];
__device__ AL __half g_yq_hi[YLEN * BSZ * HD];
__device__ AL __half g_xvT_hi[BSZ * HD * XLEN], g_xvT_lo[BSZ * HD * XLEN];
__device__ AL float  g_logits[BSZ * YLEN * XLEN];
__device__ AL __half g_attn_hi[BSZ * YLEN * XLEN];

// ===================== fused split: fp32 -> fp16 (hi [, lo]) =============
struct SplitArgs {
    const float* src[6];
    __half* hi[6];
    __half* lo[6];       // null -> hi only
    int incols[6], outld[6];
    long n4[6];
};

__global__ __launch_bounds__(256) void split_all(SplitArgs s)
{
    const int e = blockIdx.y;
    long i4 = (long)blockIdx.x * 256 + threadIdx.x;
    if (i4 >= s.n4[e]) return;
    long base = i4 * 4;
    long r = base / s.incols[e], c = base - r * s.incols[e];
    float4 v = *(const float4*)(s.src[e] + base);
    __half h0 = __float2half_rn(v.x), h1 = __float2half_rn(v.y),
           h2 = __float2half_rn(v.z), h3 = __float2half_rn(v.w);
    long off = r * s.outld[e] + c;
    __half2 hp0 = {h0, h1}, hp1 = {h2, h3};
    *(uint2*)(s.hi[e] + off) = make_uint2(*(uint32_t*)&hp0, *(uint32_t*)&hp1);
    if (s.lo[e]) {
        __half l0 = __float2half_rn(v.x - __half2float(h0));
        __half l1 = __float2half_rn(v.y - __half2float(h1));
        __half l2 = __float2half_rn(v.z - __half2float(h2));
        __half l3 = __float2half_rn(v.w - __half2float(h3));
        __half2 lp0 = {l0, l1}, lp1 = {l2, l3};
        *(uint2*)(s.lo[e] + off) = make_uint2(*(uint32_t*)&lp0, *(uint32_t*)&lp1);
    }
}

// ===================== transpose xv (x*b,h) -> (b,h,x) ===================
__global__ __launch_bounds__(256) void transpose_xv()
{
    __shared__ __half th[32][33], tl[32][33];
    int b = blockIdx.z;
    int x0 = blockIdx.x * 32, h0 = blockIdx.y * 32;
    int tx = threadIdx.x, ty = threadIdx.y;
#pragma unroll
    for (int i = ty; i < 32; i += 8) {
        long src = ((long)(x0 + i) * BSZ + b) * HD + h0 + tx;
        th[i][tx] = g_xv_hi[src];
        tl[i][tx] = g_xv_lo[src];
    }
    __syncthreads();
#pragma unroll
    for (int i = ty; i < 32; i += 8) {
        long dst = (long)b * HD * XLEN + (long)(h0 + i) * XLEN + x0 + tx;
        g_xvT_hi[dst] = th[tx][i];
        g_xvT_lo[dst] = tl[tx][i];
    }
}

// ===================== softmax: fp32 logits -> fp16 attn =================
__global__ __launch_bounds__(256) void softmax_kernel()
{
    const long row = blockIdx.x;
    const float* p = g_logits + row * XLEN;
    __half* ah = g_attn_hi + row * XLEN;
    const int tid = threadIdx.x;

    float v[8];
    float mx = -FMAXV;
#pragma unroll
    for (int i = 0; i < 8; i++) { v[i] = p[tid + (i << 8)]; mx = fmaxf(mx, v[i]); }

    __shared__ float sred[8];
#pragma unroll
    for (int o = 16; o > 0; o >>= 1) mx = fmaxf(mx, __shfl_xor_sync(0xffffffff, mx, o));
    if ((tid & 31) == 0) sred[tid >> 5] = mx;
    __syncthreads();
    mx = sred[0];
#pragma unroll
    for (int w = 1; w < 8; w++) mx = fmaxf(mx, sred[w]);
    __syncthreads();

    float s = 0.0f;
#pragma unroll
    for (int i = 0; i < 8; i++) { v[i] = expf(v[i] - mx); s += v[i]; }
#pragma unroll
    for (int o = 16; o > 0; o >>= 1) s += __shfl_xor_sync(0xffffffff, s, o);
    if ((tid & 31) == 0) sred[tid >> 5] = s;
    __syncthreads();
    s = 0.0f;
#pragma unroll
    for (int w = 0; w < 8; w++) s += sred[w];

    const float inv = 1.0f / s;
#pragma unroll
    for (int i = 0; i < 8; i++)
        ah[tid + (i << 8)] = __float2half_rn(v[i] * inv);
}

// ===================== fp16 2-term GEMM ==================================
// C[M,N] = Ah[M,K] @ (Bh+Bl)[N,K]^T
// Block 128x128, BK=32, 8 warps (2x4), warp tile 64x32, 3-stage cp.async,
// 2 CTAs/SM (72KB smem, <=128 regs).
struct GemmArgs {
    const __half *Ah, *Bh, *Bl;
    long lda, ldb, Abatch, Bbatch;
    int K;
    float* Cf;
    __half *Chi, *Clo;
    long ldc, Cbatch;
    const float* bias;
    float scale;
    const float* align;
    const int*   mask;
    const float* alignw;
};

#define STG   24576            // Ah 8K | Bh 8K | Bl 8K
#define NSTG  3
#define SMEM_BYTES (NSTG * STG)

template <int MODE>
__global__ __launch_bounds__(256, 2) void mma_gemm(GemmArgs g)
{
    extern __shared__ char smem[];
    const uint32_t sb = smem_u32(smem);
    const int tid = threadIdx.x, wid = tid >> 5, lane = tid & 31;
    const int b = blockIdx.z;
    const long m0 = (long)blockIdx.y * 128, n0 = (long)blockIdx.x * 128;
    const int wm = (wid >> 2) * 64;
    const int wn = (wid & 3) * 32;

    const __half* Ah = g.Ah + (long)b * g.Abatch;
    const __half* Bh = g.Bh + (long)b * g.Bbatch;
    const __half* Bl = g.Bl + (long)b * g.Bbatch;

    // global->shared plan: 2 x 16B chunks per thread per tensor
    const int r0c = tid >> 2,         ch0 = tid & 3;
    const int r1c = (tid + 256) >> 2, ch1 = (tid + 256) & 3;
    const uint32_t swA0 = swz(r0c, ch0), swA1 = swz(r1c, ch1);
    const long ga0 = (m0 + r0c) * g.lda + ch0 * 8;
    const long ga1 = (m0 + r1c) * g.lda + ch1 * 8;
    const long gb0 = (n0 + r0c) * g.ldb + ch0 * 8;
    const long gb1 = (n0 + r1c) * g.ldb + ch1 * 8;

    const int NT = g.K >> 5;

    // ldmatrix addressing
    const int a_r = (lane & 15), a_c = (lane >> 4);
    const int b_r = (lane & 7) + ((lane >> 4) & 1) * 8, b_c = (lane >> 3) & 1;

    float acc[4][4][4];
#pragma unroll
    for (int i = 0; i < 4; i++)
#pragma unroll
        for (int j = 0; j < 4; j++)
#pragma unroll
            for (int k = 0; k < 4; k++) acc[i][j][k] = 0.0f;

    auto load_stage = [&](int s, int it) {
        const long k0 = (long)it << 5;
        const uint32_t base = sb + s * STG;
        CP16(base + swA0,         (const char*)(Ah + ga0 + k0));
        CP16(base + swA1,         (const char*)(Ah + ga1 + k0));
        CP16(base + 8192  + swA0, (const char*)(Bh + gb0 + k0));
        CP16(base + 8192  + swA1, (const char*)(Bh + gb1 + k0));
        CP16(base + 16384 + swA0, (const char*)(Bl + gb0 + k0));
        CP16(base + 16384 + swA1, (const char*)(Bl + gb1 + k0));
        CP_COMMIT();
    };

    load_stage(0, 0);
    load_stage(1, 1);

    int cur = 0, nxt = 2;
    for (int it = 0; it < NT; ++it) {
        CP_WAIT1();
        __syncthreads();
        if (it + 2 < NT) {
            load_stage(nxt, it + 2);
            if (++nxt == NSTG) nxt = 0;
        } else CP_COMMIT();

        const uint32_t st = sb + cur * STG;
        if (++cur == NSTG) cur = 0;
#pragma unroll
        for (int ks = 0; ks < 2; ks++) {
            const int kc = ks * 2;
            uint32_t ah[4][4], bh[2][4], bl[2][4];
#pragma unroll
            for (int mi = 0; mi < 4; mi++) {
                const uint32_t ao = swz(wm + mi * 16 + a_r, kc + a_c);
                LDSM4(ah[mi], st + ao);
            }
#pragma unroll
            for (int nb = 0; nb < 2; nb++) {
                const uint32_t bo = swz(wn + nb * 16 + b_r, kc + b_c);
                LDSM4(bh[nb], st + 8192  + bo);
                LDSM4(bl[nb], st + 16384 + bo);
            }
#pragma unroll
            for (int mi = 0; mi < 4; mi++)
#pragma unroll
                for (int ni = 0; ni < 4; ni++) {
                    const int nb = ni >> 1, sub = (ni & 1) * 2;
                    MMA_F16(acc[mi][ni], ah[mi], bh[nb][sub], bh[nb][sub + 1]);
                    MMA_F16(acc[mi][ni], ah[mi], bl[nb][sub], bl[nb][sub + 1]);
                }
        }
        __syncthreads();
    }

    // ===================== epilogue =====================
    const float sig = (MODE == 1) ? (1.0f / (1.0f + expf(-__ldg(g.alignw)))) : 0.0f;

#pragma unroll
    for (int mi = 0; mi < 4; mi++) {
#pragma unroll
        for (int ni = 0; ni < 4; ni++) {
#pragma unroll
            for (int h = 0; h < 2; h++) {
                const long row = m0 + wm + mi * 16 + (lane >> 2) + h * 8;
                const long col = n0 + wn + ni * 8 + (lane & 3) * 2;
                float v0 = acc[mi][ni][h * 2 + 0];
                float v1 = acc[mi][ni][h * 2 + 1];
                const long idx = (long)b * g.Cbatch + row * g.ldc + col;
                if (MODE == 0) {
                    if (g.bias) { v0 += g.bias[col]; v1 += g.bias[col + 1]; }
                    v0 *= g.scale; v1 *= g.scale;
                    __half h0 = __float2half_rn(v0), h1 = __float2half_rn(v1);
                    __half2 hh = {h0, h1};
                    *(uint32_t*)(g.Chi + idx) = *(uint32_t*)&hh;
                    if (g.Clo) {
                        __half l0 = __float2half_rn(v0 - __half2float(h0));
                        __half l1 = __float2half_rn(v1 - __half2float(h1));
                        __half2 ll = {l0, l1};
                        *(uint32_t*)(g.Clo + idx) = *(uint32_t*)&ll;
                    }
                } else if (MODE == 1) {
                    float2 av = *(const float2*)(g.align + idx);
                    int2 mv = *(const int2*)(g.mask + idx);
                    float o0 = v0 + sig * av.x;
                    float o1 = v1 + sig * av.y;
                    o0 = fmaxf(o0, -FMAXV);
                    o1 = fmaxf(o1, -FMAXV);
                    if (mv.x != 0) o0 = fmaxf(o0 - FMAXV, -FMAXV);
                    if (mv.y != 0) o1 = fmaxf(o1 - FMAXV, -FMAXV);
                    *(float2*)(g.Cf + idx) = make_float2(o0, o1);
                } else {
                    v0 += g.bias[col];
                    v1 += g.bias[col + 1];
                    *(float2*)(g.Cf + idx) = make_float2(v0, v1);
                }
            }
        }
    }
}

// ===================== launch ============================================
extern "C" void kernel_launch(void* const* d_in, const int* in_sizes, int n_in,
                              void* d_out, int out_size)
{
    const float* X         = (const float*)d_in[0];
    const float* Y         = (const float*)d_in[1];
    const float* alignment = (const float*)d_in[2];
    const int*   mask      = (const int*)d_in[3];
    const float* Xk_w      = (const float*)d_in[4];
    const float* Xk_b      = (const float*)d_in[5];
    const float* Xv_w      = (const float*)d_in[6];
    const float* Xv_b      = (const float*)d_in[7];
    const float* Yq_w      = (const float*)d_in[8];
    const float* Yq_b      = (const float*)d_in[9];
    const float* Yw_w      = (const float*)d_in[10];
    const float* Yw_b      = (const float*)d_in[11];
    const float* align_w   = (const float*)d_in[12];
    float* out = (float*)d_out;

    cudaFuncSetAttribute(mma_gemm<0>, cudaFuncAttributeMaxDynamicSharedMemorySize, SMEM_BYTES);
    cudaFuncSetAttribute(mma_gemm<1>, cudaFuncAttributeMaxDynamicSharedMemorySize, SMEM_BYTES);
    cudaFuncSetAttribute(mma_gemm<2>, cudaFuncAttributeMaxDynamicSharedMemorySize, SMEM_BYTES);

#define SYM(p, s) do { void* _t; cudaGetSymbolAddress(&_t, s); p = (decltype(p))_t; } while (0)
    __half *Xhi, *cat_hi, *Xkw_hi, *Xkw_lo, *Xvw_hi, *Xvw_lo,
        *Yqw_hi, *Yqw_lo, *Yww_hi, *Yww_lo, *xk_hi, *xk_lo, *xv_hi, *xv_lo,
        *yq_hi, *xvT_hi, *xvT_lo, *attn_hi;
    float* logits;
    SYM(Xhi, g_Xhi); SYM(cat_hi, g_cat_hi);
    SYM(Xkw_hi, g_Xkw_hi); SYM(Xkw_lo, g_Xkw_lo); SYM(Xvw_hi, g_Xvw_hi); SYM(Xvw_lo, g_Xvw_lo);
    SYM(Yqw_hi, g_Yqw_hi); SYM(Yqw_lo, g_Yqw_lo); SYM(Yww_hi, g_Yww_hi); SYM(Yww_lo, g_Yww_lo);
    SYM(xk_hi, g_xk_hi); SYM(xk_lo, g_xk_lo); SYM(xv_hi, g_xv_hi); SYM(xv_lo, g_xv_lo);
    SYM(yq_hi, g_yq_hi); SYM(xvT_hi, g_xvT_hi); SYM(xvT_lo, g_xvT_lo);
    SYM(attn_hi, g_attn_hi); SYM(logits, g_logits);

    // ---- fused split (1 launch) ----
    SplitArgs sa;
    sa.src[0] = X;    sa.hi[0] = Xhi;    sa.lo[0] = nullptr;
    sa.incols[0] = XD;   sa.outld[0] = XD;   sa.n4[0] = (long)XLEN * BSZ * XD / 4;
    sa.src[1] = Y;    sa.hi[1] = cat_hi; sa.lo[1] = nullptr;
    sa.incols[1] = YD;   sa.outld[1] = CATD; sa.n4[1] = (long)YLEN * BSZ * YD / 4;
    sa.src[2] = Xk_w; sa.hi[2] = Xkw_hi; sa.lo[2] = Xkw_lo;
    sa.incols[2] = XD;   sa.outld[2] = XD;   sa.n4[2] = (long)HD * XD / 4;
    sa.src[3] = Xv_w; sa.hi[3] = Xvw_hi; sa.lo[3] = Xvw_lo;
    sa.incols[3] = XD;   sa.outld[3] = XD;   sa.n4[3] = (long)HD * XD / 4;
    sa.src[4] = Yq_w; sa.hi[4] = Yqw_hi; sa.lo[4] = Yqw_lo;
    sa.incols[4] = YD;   sa.outld[4] = YD;   sa.n4[4] = (long)HD * YD / 4;
    sa.src[5] = Yw_w; sa.hi[5] = Yww_hi; sa.lo[5] = Yww_lo;
    sa.incols[5] = CATD; sa.outld[5] = CATD; sa.n4[5] = (long)YOUT * CATD / 4;
    long maxn4 = sa.n4[0];
    for (int i = 1; i < 6; i++) if (sa.n4[i] > maxn4) maxn4 = sa.n4[i];
    split_all<<<dim3((unsigned)((maxn4 + 255) / 256), 6), 256>>>(sa);

    GemmArgs a = {};

    // ---- xk = X @ Xk_w^T + b : M=16384 N=512 K=1024 (hi+lo out) ----
    a.Ah = Xhi; a.lda = XD; a.Abatch = 0;
    a.Bh = Xkw_hi; a.Bl = Xkw_lo; a.ldb = XD; a.Bbatch = 0;
    a.K = XD; a.Chi = xk_hi; a.Clo = xk_lo; a.ldc = HD; a.Cbatch = 0;
    a.bias = Xk_b; a.scale = 1.0f;
    mma_gemm<0><<<dim3(HD / 128, XLEN * BSZ / 128, 1), 256, SMEM_BYTES>>>(a);

    // ---- xv = X @ Xv_w^T + b (hi+lo) ----
    a.Bh = Xvw_hi; a.Bl = Xvw_lo; a.Chi = xv_hi; a.Clo = xv_lo; a.bias = Xv_b;
    mma_gemm<0><<<dim3(HD / 128, XLEN * BSZ / 128, 1), 256, SMEM_BYTES>>>(a);

    // ---- yq = (Y @ Yq_w^T + b) / sqrt(HD) : M=8192 N=512 K=1024 (hi only) ----
    a.Ah = cat_hi; a.lda = CATD;
    a.Bh = Yqw_hi; a.Bl = Yqw_lo; a.ldb = YD;
    a.Chi = yq_hi; a.Clo = nullptr; a.bias = Yq_b; a.scale = INV_SQRT_HD;
    mma_gemm<0><<<dim3(HD / 128, YLEN * BSZ / 128, 1), 256, SMEM_BYTES>>>(a);

    // ---- transpose xv -> (b,h,x) ----
    transpose_xv<<<dim3(XLEN / 32, HD / 32, BSZ), dim3(32, 8)>>>();

    // ---- logits[b,y,x] : per batch M=1024 N=2048 K=512 ----
    a = {};
    a.Ah = yq_hi; a.lda = BSZ * HD; a.Abatch = HD;
    a.Bh = xk_hi; a.Bl = xk_lo; a.ldb = BSZ * HD; a.Bbatch = HD;
    a.K = HD; a.Cf = logits; a.ldc = XLEN; a.Cbatch = (long)YLEN * XLEN;
    a.align = alignment; a.mask = mask; a.alignw = align_w; a.scale = 1.0f;
    mma_gemm<1><<<dim3(XLEN / 128, YLEN / 128, BSZ), 256, SMEM_BYTES>>>(a);

    // ---- softmax -> attn (hi only) ----
    softmax_kernel<<<BSZ * YLEN, 256>>>();

    // ---- attn_feat = attn @ xvT^T -> cat[:, 1024:1536] ----
    a = {};
    a.Ah = attn_hi; a.lda = XLEN; a.Abatch = (long)YLEN * XLEN;
    a.Bh = xvT_hi; a.Bl = xvT_lo; a.ldb = XLEN; a.Bbatch = (long)HD * XLEN;
    a.K = XLEN; a.Chi = cat_hi + YD; a.Clo = nullptr;
    a.ldc = (long)BSZ * CATD; a.Cbatch = CATD; a.bias = nullptr; a.scale = 1.0f;
    mma_gemm<0><<<dim3(HD / 128, YLEN / 128, BSZ), 256, SMEM_BYTES>>>(a);

    // ---- out = cat @ Yw_w^T + b : M=8192 N=1024 K=1536 ----
    a = {};
    a.Ah = cat_hi; a.lda = CATD; a.Abatch = 0;
    a.Bh = Yww_hi; a.Bl = Yww_lo; a.ldb = CATD; a.Bbatch = 0;
    a.K = CATD; a.Cf = out; a.ldc = YOUT; a.Cbatch = 0; a.bias = Yw_b; a.scale = 1.0f;
    mma_gemm<2><<<dim3(YOUT / 128, YLEN * BSZ / 128, 1), 256, SMEM_BYTES>>>(a);
}

// round 6
// speedup vs baseline: 4.9046x; 1.1804x over previous
#include <cuda_runtime.h>
#include <cuda_fp16.h>
#include <math.h>
#include <stdint.h>

#define XLEN 2048
#define YLEN 1024
#define BSZ  8
#define XD   1024
#define YD   1024
#define HD   512
#define YOUT 1024
#define CATD (YD + HD)
#define FMAXV 3.402823466e38f
#define INV_SQRT_HD 0.04419417382415922f

// ===================== PTX helpers =====================
__device__ __forceinline__ uint32_t smem_u32(const void* p) {
    uint32_t a;
    asm("{ .reg .u64 t; cvta.to.shared.u64 t, %1; cvt.u32.u64 %0, t; }" : "=r"(a) : "l"(p));
    return a;
}
#define CP16(dst, src) \
    asm volatile("cp.async.cg.shared.global [%0], [%1], 16;" :: "r"(dst), "l"(src))
#define CP_COMMIT() asm volatile("cp.async.commit_group;")

#define LDSM4(r, a) \
    asm volatile("ldmatrix.sync.aligned.m8n8.x4.shared.b16 {%0,%1,%2,%3}, [%4];" \
        : "=r"((r)[0]), "=r"((r)[1]), "=r"((r)[2]), "=r"((r)[3]) : "r"(a))

#define MMA_F16(d, a, b0v, b1v) \
    asm volatile("mma.sync.aligned.m16n8k16.row.col.f32.f16.f16.f32 " \
        "{%0,%1,%2,%3}, {%4,%5,%6,%7}, {%8,%9}, {%0,%1,%2,%3};" \
        : "+f"((d)[0]), "+f"((d)[1]), "+f"((d)[2]), "+f"((d)[3]) \
        : "r"((a)[0]), "r"((a)[1]), "r"((a)[2]), "r"((a)[3]), "r"(b0v), "r"(b1v))

// SMEM tile: 128 rows x 32 f16 (64B/row, 4 x 16B chunks), bank-conflict swizzle.
__device__ __forceinline__ uint32_t swz(int row, int chunk) {
    return (uint32_t)(row * 64 + ((chunk ^ ((row >> 1) & 3)) << 4));
}

// ===================== scratch (device globals) ==========================
#define AL __align__(16)
__device__ AL __half g_Xhi[XLEN * BSZ * XD];
__device__ AL __half g_cat_hi[YLEN * BSZ * CATD];
__device__ AL __half g_Xkw_hi[HD * XD],  g_Xkw_lo[HD * XD];
__device__ AL __half g_Xvw_hi[HD * XD],  g_Xvw_lo[HD * XD];
__device__ AL __half g_Yqw_hi[HD * YD],  g_Yqw_lo[HD * YD];
__device__ AL __half g_Yww_hi[YOUT * CATD];
__device__ AL __half g_xk_hi[XLEN * BSZ * HD], g_xk_lo[XLEN * BSZ * HD];
__device__ AL __half g_xv_hi[XLEN * BSZ * HD];
__device__ AL __half g_yq_hi[YLEN * BSZ * HD];
__device__ AL __half g_xvT_hi[BSZ * HD * XLEN];
__device__ AL float  g_logits[BSZ * YLEN * XLEN];
__device__ AL __half g_attn_hi[BSZ * YLEN * XLEN];

// ===================== fused split: fp32 -> fp16 (hi [, lo]) =============
struct SplitArgs {
    const float* src[6];
    __half* hi[6];
    __half* lo[6];       // null -> hi only
    int incols[6], outld[6];
    long n4[6];
};

__global__ __launch_bounds__(256) void split_all(SplitArgs s)
{
    const int e = blockIdx.y;
    long i4 = (long)blockIdx.x * 256 + threadIdx.x;
    if (i4 >= s.n4[e]) return;
    long base = i4 * 4;
    long r = base / s.incols[e], c = base - r * s.incols[e];
    float4 v = *(const float4*)(s.src[e] + base);
    __half h0 = __float2half_rn(v.x), h1 = __float2half_rn(v.y),
           h2 = __float2half_rn(v.z), h3 = __float2half_rn(v.w);
    long off = r * s.outld[e] + c;
    __half2 hp0 = {h0, h1}, hp1 = {h2, h3};
    *(uint2*)(s.hi[e] + off) = make_uint2(*(uint32_t*)&hp0, *(uint32_t*)&hp1);
    if (s.lo[e]) {
        __half l0 = __float2half_rn(v.x - __half2float(h0));
        __half l1 = __float2half_rn(v.y - __half2float(h1));
        __half l2 = __float2half_rn(v.z - __half2float(h2));
        __half l3 = __float2half_rn(v.w - __half2float(h3));
        __half2 lp0 = {l0, l1}, lp1 = {l2, l3};
        *(uint2*)(s.lo[e] + off) = make_uint2(*(uint32_t*)&lp0, *(uint32_t*)&lp1);
    }
}

// ===================== transpose xv (x*b,h) -> (b,h,x) ===================
__global__ __launch_bounds__(256) void transpose_xv()
{
    __shared__ __half th[32][33];
    int b = blockIdx.z;
    int x0 = blockIdx.x * 32, h0 = blockIdx.y * 32;
    int tx = threadIdx.x, ty = threadIdx.y;
#pragma unroll
    for (int i = ty; i < 32; i += 8) {
        long src = ((long)(x0 + i) * BSZ + b) * HD + h0 + tx;
        th[i][tx] = g_xv_hi[src];
    }
    __syncthreads();
#pragma unroll
    for (int i = ty; i < 32; i += 8) {
        long dst = (long)b * HD * XLEN + (long)(h0 + i) * XLEN + x0 + tx;
        g_xvT_hi[dst] = th[tx][i];
    }
}

// ===================== softmax: fp32 logits -> fp16 attn =================
__global__ __launch_bounds__(256) void softmax_kernel()
{
    const long row = blockIdx.x;
    const float* p = g_logits + row * XLEN;
    __half* ah = g_attn_hi + row * XLEN;
    const int tid = threadIdx.x;

    float v[8];
    float mx = -FMAXV;
#pragma unroll
    for (int i = 0; i < 8; i++) { v[i] = p[tid + (i << 8)]; mx = fmaxf(mx, v[i]); }

    __shared__ float sred[8];
#pragma unroll
    for (int o = 16; o > 0; o >>= 1) mx = fmaxf(mx, __shfl_xor_sync(0xffffffff, mx, o));
    if ((tid & 31) == 0) sred[tid >> 5] = mx;
    __syncthreads();
    mx = sred[0];
#pragma unroll
    for (int w = 1; w < 8; w++) mx = fmaxf(mx, sred[w]);
    __syncthreads();

    float s = 0.0f;
#pragma unroll
    for (int i = 0; i < 8; i++) { v[i] = expf(v[i] - mx); s += v[i]; }
#pragma unroll
    for (int o = 16; o > 0; o >>= 1) s += __shfl_xor_sync(0xffffffff, s, o);
    if ((tid & 31) == 0) sred[tid >> 5] = s;
    __syncthreads();
    s = 0.0f;
#pragma unroll
    for (int w = 0; w < 8; w++) s += sred[w];

    const float inv = 1.0f / s;
#pragma unroll
    for (int i = 0; i < 8; i++)
        ah[tid + (i << 8)] = __float2half_rn(v[i] * inv);
}

// ===================== fp16 GEMM (1 or 2 B-terms) ========================
// C[M,N] = Ah[M,K] @ (Bh [+Bl])[N,K]^T
// Block 128x128, BK=32, 8 warps (2x4), warp tile 64x32, cp.async pipeline.
// TERMS=2: 3 stages x 24KB; TERMS=1: 4 stages x 16KB. Single sync per iter.
struct GemmArgs {
    const __half *Ah, *Bh, *Bl;
    long lda, ldb, Abatch, Bbatch;
    int K;
    float* Cf;
    __half *Chi, *Clo;
    long ldc, Cbatch;
    const float* bias;
    float scale;
    const float* align;
    const int*   mask;
    const float* alignw;
};

template <int MODE, int TERMS>
__global__ __launch_bounds__(256, 2) void mma_gemm(GemmArgs g)
{
    constexpr int STG  = (TERMS == 2) ? 24576 : 16384;
    constexpr int NSTG = (TERMS == 2) ? 3 : 4;
    constexpr int WAITN = NSTG - 2;

    extern __shared__ char smem[];
    const uint32_t sb = smem_u32(smem);
    const int tid = threadIdx.x, wid = tid >> 5, lane = tid & 31;
    const int b = blockIdx.z;
    const long m0 = (long)blockIdx.y * 128, n0 = (long)blockIdx.x * 128;
    const int wm = (wid >> 2) * 64;
    const int wn = (wid & 3) * 32;

    const __half* Ah = g.Ah + (long)b * g.Abatch;
    const __half* Bh = g.Bh + (long)b * g.Bbatch;
    const __half* Bl = g.Bl ? g.Bl + (long)b * g.Bbatch : (const __half*)0;

    const int r0c = tid >> 2,         ch0 = tid & 3;
    const int r1c = (tid + 256) >> 2, ch1 = (tid + 256) & 3;
    const uint32_t swA0 = swz(r0c, ch0), swA1 = swz(r1c, ch1);
    const long ga0 = (m0 + r0c) * g.lda + ch0 * 8;
    const long ga1 = (m0 + r1c) * g.lda + ch1 * 8;
    const long gb0 = (n0 + r0c) * g.ldb + ch0 * 8;
    const long gb1 = (n0 + r1c) * g.ldb + ch1 * 8;

    const int NT = g.K >> 5;

    const int a_r = (lane & 15), a_c = (lane >> 4);
    const int b_r = (lane & 7) + ((lane >> 4) & 1) * 8, b_c = (lane >> 3) & 1;

    float acc[4][4][4];
#pragma unroll
    for (int i = 0; i < 4; i++)
#pragma unroll
        for (int j = 0; j < 4; j++)
#pragma unroll
            for (int k = 0; k < 4; k++) acc[i][j][k] = 0.0f;

    auto load_stage = [&](int s, int it) {
        const long k0 = (long)it << 5;
        const uint32_t base = sb + s * STG;
        CP16(base + swA0,        (const char*)(Ah + ga0 + k0));
        CP16(base + swA1,        (const char*)(Ah + ga1 + k0));
        CP16(base + 8192 + swA0, (const char*)(Bh + gb0 + k0));
        CP16(base + 8192 + swA1, (const char*)(Bh + gb1 + k0));
        if (TERMS == 2) {
            CP16(base + 16384 + swA0, (const char*)(Bl + gb0 + k0));
            CP16(base + 16384 + swA1, (const char*)(Bl + gb1 + k0));
        }
        CP_COMMIT();
    };

#pragma unroll
    for (int p = 0; p < NSTG - 1; p++) load_stage(p, p);

    int cur = 0, nxt = NSTG - 1;
    for (int it = 0; it < NT; ++it) {
        asm volatile("cp.async.wait_group %0;" :: "n"(WAITN));
        __syncthreads();
        // Prefetch into the stage consumed at iter it-1 (all warps are past it:
        // the sync above proves it), so no trailing barrier is needed.
        if (it + NSTG - 1 < NT) {
            load_stage(nxt, it + NSTG - 1);
            if (++nxt == NSTG) nxt = 0;
        } else CP_COMMIT();

        const uint32_t st = sb + cur * STG;
        if (++cur == NSTG) cur = 0;
#pragma unroll
        for (int ks = 0; ks < 2; ks++) {
            const int kc = ks * 2;
            uint32_t ah[4][4], bh[2][4], bl[2][4];
#pragma unroll
            for (int mi = 0; mi < 4; mi++) {
                const uint32_t ao = swz(wm + mi * 16 + a_r, kc + a_c);
                LDSM4(ah[mi], st + ao);
            }
#pragma unroll
            for (int nb = 0; nb < 2; nb++) {
                const uint32_t bo = swz(wn + nb * 16 + b_r, kc + b_c);
                LDSM4(bh[nb], st + 8192 + bo);
                if (TERMS == 2) LDSM4(bl[nb], st + 16384 + bo);
            }
#pragma unroll
            for (int mi = 0; mi < 4; mi++)
#pragma unroll
                for (int ni = 0; ni < 4; ni++) {
                    const int nb = ni >> 1, sub = (ni & 1) * 2;
                    MMA_F16(acc[mi][ni], ah[mi], bh[nb][sub], bh[nb][sub + 1]);
                    if (TERMS == 2)
                        MMA_F16(acc[mi][ni], ah[mi], bl[nb][sub], bl[nb][sub + 1]);
                }
        }
    }
    __syncthreads();

    // ===================== epilogue =====================
    const float sig = (MODE == 1) ? (1.0f / (1.0f + expf(-__ldg(g.alignw)))) : 0.0f;

#pragma unroll
    for (int mi = 0; mi < 4; mi++) {
#pragma unroll
        for (int ni = 0; ni < 4; ni++) {
#pragma unroll
            for (int h = 0; h < 2; h++) {
                const long row = m0 + wm + mi * 16 + (lane >> 2) + h * 8;
                const long col = n0 + wn + ni * 8 + (lane & 3) * 2;
                float v0 = acc[mi][ni][h * 2 + 0];
                float v1 = acc[mi][ni][h * 2 + 1];
                const long idx = (long)b * g.Cbatch + row * g.ldc + col;
                if (MODE == 0) {
                    if (g.bias) { v0 += g.bias[col]; v1 += g.bias[col + 1]; }
                    v0 *= g.scale; v1 *= g.scale;
                    __half h0 = __float2half_rn(v0), h1 = __float2half_rn(v1);
                    __half2 hh = {h0, h1};
                    *(uint32_t*)(g.Chi + idx) = *(uint32_t*)&hh;
                    if (g.Clo) {
                        __half l0 = __float2half_rn(v0 - __half2float(h0));
                        __half l1 = __float2half_rn(v1 - __half2float(h1));
                        __half2 ll = {l0, l1};
                        *(uint32_t*)(g.Clo + idx) = *(uint32_t*)&ll;
                    }
                } else if (MODE == 1) {
                    float2 av = *(const float2*)(g.align + idx);
                    int2 mv = *(const int2*)(g.mask + idx);
                    float o0 = v0 + sig * av.x;
                    float o1 = v1 + sig * av.y;
                    o0 = fmaxf(o0, -FMAXV);
                    o1 = fmaxf(o1, -FMAXV);
                    if (mv.x != 0) o0 = fmaxf(o0 - FMAXV, -FMAXV);
                    if (mv.y != 0) o1 = fmaxf(o1 - FMAXV, -FMAXV);
                    *(float2*)(g.Cf + idx) = make_float2(o0, o1);
                } else {
                    v0 += g.bias[col];
                    v1 += g.bias[col + 1];
                    *(float2*)(g.Cf + idx) = make_float2(v0, v1);
                }
            }
        }
    }
}

// ===================== launch ============================================
extern "C" void kernel_launch(void* const* d_in, const int* in_sizes, int n_in,
                              void* d_out, int out_size)
{
    const float* X         = (const float*)d_in[0];
    const float* Y         = (const float*)d_in[1];
    const float* alignment = (const float*)d_in[2];
    const int*   mask      = (const int*)d_in[3];
    const float* Xk_w      = (const float*)d_in[4];
    const float* Xk_b      = (const float*)d_in[5];
    const float* Xv_w      = (const float*)d_in[6];
    const float* Xv_b      = (const float*)d_in[7];
    const float* Yq_w      = (const float*)d_in[8];
    const float* Yq_b      = (const float*)d_in[9];
    const float* Yw_w      = (const float*)d_in[10];
    const float* Yw_b      = (const float*)d_in[11];
    const float* align_w   = (const float*)d_in[12];
    float* out = (float*)d_out;

    const int SM2 = 3 * 24576;   // TERMS=2
    const int SM1 = 4 * 16384;   // TERMS=1
    cudaFuncSetAttribute((const void*)mma_gemm<0, 2>, cudaFuncAttributeMaxDynamicSharedMemorySize, SM2);
    cudaFuncSetAttribute((const void*)mma_gemm<1, 2>, cudaFuncAttributeMaxDynamicSharedMemorySize, SM2);
    cudaFuncSetAttribute((const void*)mma_gemm<0, 1>, cudaFuncAttributeMaxDynamicSharedMemorySize, SM1);
    cudaFuncSetAttribute((const void*)mma_gemm<2, 1>, cudaFuncAttributeMaxDynamicSharedMemorySize, SM1);

#define SYM(p, s) do { void* _t; cudaGetSymbolAddress(&_t, s); p = (decltype(p))_t; } while (0)
    __half *Xhi, *cat_hi, *Xkw_hi, *Xkw_lo, *Xvw_hi, *Xvw_lo,
        *Yqw_hi, *Yqw_lo, *Yww_hi, *xk_hi, *xk_lo, *xv_hi,
        *yq_hi, *xvT_hi, *attn_hi;
    float* logits;
    SYM(Xhi, g_Xhi); SYM(cat_hi, g_cat_hi);
    SYM(Xkw_hi, g_Xkw_hi); SYM(Xkw_lo, g_Xkw_lo); SYM(Xvw_hi, g_Xvw_hi); SYM(Xvw_lo, g_Xvw_lo);
    SYM(Yqw_hi, g_Yqw_hi); SYM(Yqw_lo, g_Yqw_lo); SYM(Yww_hi, g_Yww_hi);
    SYM(xk_hi, g_xk_hi); SYM(xk_lo, g_xk_lo); SYM(xv_hi, g_xv_hi);
    SYM(yq_hi, g_yq_hi); SYM(xvT_hi, g_xvT_hi);
    SYM(attn_hi, g_attn_hi); SYM(logits, g_logits);

    // ---- fused split (1 launch) ----
    SplitArgs sa;
    sa.src[0] = X;    sa.hi[0] = Xhi;    sa.lo[0] = nullptr;
    sa.incols[0] = XD;   sa.outld[0] = XD;   sa.n4[0] = (long)XLEN * BSZ * XD / 4;
    sa.src[1] = Y;    sa.hi[1] = cat_hi; sa.lo[1] = nullptr;
    sa.incols[1] = YD;   sa.outld[1] = CATD; sa.n4[1] = (long)YLEN * BSZ * YD / 4;
    sa.src[2] = Xk_w; sa.hi[2] = Xkw_hi; sa.lo[2] = Xkw_lo;
    sa.incols[2] = XD;   sa.outld[2] = XD;   sa.n4[2] = (long)HD * XD / 4;
    sa.src[3] = Xv_w; sa.hi[3] = Xvw_hi; sa.lo[3] = Xvw_lo;
    sa.incols[3] = XD;   sa.outld[3] = XD;   sa.n4[3] = (long)HD * XD / 4;
    sa.src[4] = Yq_w; sa.hi[4] = Yqw_hi; sa.lo[4] = Yqw_lo;
    sa.incols[4] = YD;   sa.outld[4] = YD;   sa.n4[4] = (long)HD * YD / 4;
    sa.src[5] = Yw_w; sa.hi[5] = Yww_hi; sa.lo[5] = nullptr;
    sa.incols[5] = CATD; sa.outld[5] = CATD; sa.n4[5] = (long)YOUT * CATD / 4;
    long maxn4 = sa.n4[0];
    for (int i = 1; i < 6; i++) if (sa.n4[i] > maxn4) maxn4 = sa.n4[i];
    split_all<<<dim3((unsigned)((maxn4 + 255) / 256), 6), 256>>>(sa);

    GemmArgs a = {};

    // ---- xk = X @ Xk_w^T + b : M=16384 N=512 K=1024 (hi+lo out) ----
    a.Ah = Xhi; a.lda = XD; a.Abatch = 0;
    a.Bh = Xkw_hi; a.Bl = Xkw_lo; a.ldb = XD; a.Bbatch = 0;
    a.K = XD; a.Chi = xk_hi; a.Clo = xk_lo; a.ldc = HD; a.Cbatch = 0;
    a.bias = Xk_b; a.scale = 1.0f;
    mma_gemm<0, 2><<<dim3(HD / 128, XLEN * BSZ / 128, 1), 256, SM2>>>(a);

    // ---- xv = X @ Xv_w^T + b (hi out) ----
    a.Bh = Xvw_hi; a.Bl = Xvw_lo; a.Chi = xv_hi; a.Clo = nullptr; a.bias = Xv_b;
    mma_gemm<0, 2><<<dim3(HD / 128, XLEN * BSZ / 128, 1), 256, SM2>>>(a);

    // ---- yq = (Y @ Yq_w^T + b) / sqrt(HD) : M=8192 N=512 K=1024 (hi out) ----
    a.Ah = cat_hi; a.lda = CATD;
    a.Bh = Yqw_hi; a.Bl = Yqw_lo; a.ldb = YD;
    a.Chi = yq_hi; a.Clo = nullptr; a.bias = Yq_b; a.scale = INV_SQRT_HD;
    mma_gemm<0, 2><<<dim3(HD / 128, YLEN * BSZ / 128, 1), 256, SM2>>>(a);

    // ---- transpose xv -> (b,h,x) ----
    transpose_xv<<<dim3(XLEN / 32, HD / 32, BSZ), dim3(32, 8)>>>();

    // ---- logits[b,y,x] : per batch M=1024 N=2048 K=512 ----
    a = {};
    a.Ah = yq_hi; a.lda = BSZ * HD; a.Abatch = HD;
    a.Bh = xk_hi; a.Bl = xk_lo; a.ldb = BSZ * HD; a.Bbatch = HD;
    a.K = HD; a.Cf = logits; a.ldc = XLEN; a.Cbatch = (long)YLEN * XLEN;
    a.align = alignment; a.mask = mask; a.alignw = align_w; a.scale = 1.0f;
    mma_gemm<1, 2><<<dim3(XLEN / 128, YLEN / 128, BSZ), 256, SM2>>>(a);

    // ---- softmax -> attn (hi only) ----
    softmax_kernel<<<BSZ * YLEN, 256>>>();

    // ---- attn_feat = attn @ xvT^T -> cat[:, 1024:1536] (1-term) ----
    a = {};
    a.Ah = attn_hi; a.lda = XLEN; a.Abatch = (long)YLEN * XLEN;
    a.Bh = xvT_hi; a.Bl = nullptr; a.ldb = XLEN; a.Bbatch = (long)HD * XLEN;
    a.K = XLEN; a.Chi = cat_hi + YD; a.Clo = nullptr;
    a.ldc = (long)BSZ * CATD; a.Cbatch = CATD; a.bias = nullptr; a.scale = 1.0f;
    mma_gemm<0, 1><<<dim3(HD / 128, YLEN / 128, BSZ), 256, SM1>>>(a);

    // ---- out = cat @ Yw_w^T + b : M=8192 N=1024 K=1536 (1-term) ----
    a = {};
    a.Ah = cat_hi; a.lda = CATD; a.Abatch = 0;
    a.Bh = Yww_hi; a.Bl = nullptr; a.ldb = CATD; a.Bbatch = 0;
    a.K = CATD; a.Cf = out; a.ldc = YOUT; a.Cbatch = 0; a.bias = Yw_b; a.scale = 1.0f;
    mma_gemm<2, 1><<<dim3(YOUT / 128, YLEN * BSZ / 128, 1), 256, SM1>>>(a);
}